// round 9
// baseline (speedup 1.0000x reference)
#include <cuda_runtime.h>
#include <cuda_bf16.h>
#include <cstdint>
#include <math.h>

// Problem constants
#define BATCH 2
#define SEQ   2048
#define EMB   1024
#define HEADS 16
#define HDIM  64
#define MROWS (BATCH * SEQ)   // 4096

// ---------------- scratch (device globals; no allocations allowed) ---------
__device__ float g_Q[MROWS * EMB];        // Q proj: scaled, rounded, dim-permuted
__device__ float g_K[MROWS * EMB];        // K proj: rounded, dim-permuted
__device__ float g_VT[EMB * MROWS];       // V proj: transposed, token-permuted, rounded
__device__ float g_C[MROWS * EMB];        // attention out: rounded, dim-permuted
__device__ float g_WT[4][EMB * EMB];      // W^T: rounded, k-permuted
__device__ float g_X[3][MROWS * EMB];     // xq/xk/xv: rounded, k-permuted

#define QSCALE 0.18033688f   // 0.125 * log2(e)

// ============================================================================
// helpers
// ============================================================================
__device__ __forceinline__ uint32_t smem_u32(const void* p) {
    uint32_t a;
    asm("{ .reg .u64 t; cvta.to.shared.u64 t, %1; cvt.u32.u64 %0, t; }"
        : "=r"(a) : "l"(p));
    return a;
}

__device__ __forceinline__ uint32_t f32_to_tf32(float f) {
    uint32_t r;
    asm("cvt.rna.tf32.f32 %0, %1;" : "=r"(r) : "f"(f));
    return r;
}
__device__ __forceinline__ float tf32r(float f) {
    return __uint_as_float(f32_to_tf32(f));
}

__device__ __forceinline__ float ex2(float x) {
    float r;
    asm("ex2.approx.f32 %0, %1;" : "=f"(r) : "f"(x));
    return r;
}

#define MMA_TF32(c, a, b)                                                     \
    asm volatile("mma.sync.aligned.m16n8k8.row.col.f32.tf32.tf32.f32 "        \
                 "{%0,%1,%2,%3}, {%4,%5,%6,%7}, {%8,%9}, {%0,%1,%2,%3};"      \
                 : "+f"((c)[0]), "+f"((c)[1]), "+f"((c)[2]), "+f"((c)[3])     \
                 : "r"((a)[0]), "r"((a)[1]), "r"((a)[2]), "r"((a)[3]),        \
                   "r"((b)[0]), "r"((b)[1]))

#define LDS_V2(r0, r1, addr)                                                  \
    asm volatile("ld.shared.v2.b32 {%0,%1}, [%2];"                            \
                 : "=r"(r0), "=r"(r1) : "r"(addr))

#define CP_ASYNC16(dst, src)                                                  \
    asm volatile("cp.async.cg.shared.global [%0], [%1], 16;"                  \
                 :: "r"(dst), "l"(src))
#define CP_COMMIT() asm volatile("cp.async.commit_group;" ::: "memory")
#define CP_WAIT0()  asm volatile("cp.async.wait_group 0;" ::: "memory")

// position of k within its 8-group in the mma-friendly permuted layout
__device__ __forceinline__ int perm8(int k) {
    return ((k & 3) << 1) | ((k & 7) >> 2);
}

// ============================================================================
// Pre-round + k-permute: Y[8i + perm8(j)] = tf32r(X[8i + j])
// ============================================================================
__global__ void __launch_bounds__(256)
preround_perm_kernel(const float* __restrict__ X, float* __restrict__ Y)
{
    size_t i = ((size_t)blockIdx.x * 256 + threadIdx.x) * 8;
    float4 a = *(const float4*)&X[i];
    float4 b = *(const float4*)&X[i + 4];
    float4 o0, o1;
    o0.x = tf32r(a.x); o0.y = tf32r(b.x); o0.z = tf32r(a.y); o0.w = tf32r(b.y);
    o1.x = tf32r(a.z); o1.y = tf32r(b.z); o1.z = tf32r(a.w); o1.w = tf32r(b.w);
    *(float4*)&Y[i]     = o0;
    *(float4*)&Y[i + 4] = o1;
}

// ============================================================================
// Weight transpose + tf32 round + k-permute: WT[n][perm(k)] = tf32r(W[k][n])
// ============================================================================
__global__ void __launch_bounds__(256)
transpose_rna_kernel(const float* __restrict__ W, float* __restrict__ WT)
{
    __shared__ float tile[32][33];
    int x = blockIdx.x * 32 + threadIdx.x;
    int y = blockIdx.y * 32 + threadIdx.y;
#pragma unroll
    for (int j = 0; j < 32; j += 8)
        tile[threadIdx.y + j][threadIdx.x] = W[(size_t)(y + j) * EMB + x];
    __syncthreads();
    int xo = blockIdx.y * 32 + threadIdx.x;
    int xo_p = (xo & ~7) | perm8(xo & 7);
    int yo = blockIdx.x * 32 + threadIdx.y;
#pragma unroll
    for (int j = 0; j < 32; j += 8) {
        WT[(size_t)(yo + j) * EMB + xo_p] = tf32r(tile[threadIdx.x][threadIdx.y + j]);
    }
}

// ============================================================================
// tf32 mma.sync GEMM, cp.async staging (inputs pre-rounded + pre-permuted).
// MODE 0: plain fp32 row-major output (final projection)
// MODE 1: Q out: *QSCALE, rounded, dim-permuted
// MODE 2: K out: rounded, dim-permuted
// MODE 3: V out: transposed [n][m], token-permuted, rounded
// ============================================================================
#define GBM 128
#define GBN 128
#define GBK 32
#define RSTR 40
#define TILE_F (128 * RSTR)
#define GSMEM_TOTAL (4 * TILE_F * 4)

template <int MODE>
__global__ void __launch_bounds__(256, 2)
gemm_tf32_kernel(const float* __restrict__ A, const float* __restrict__ WT,
                 const float* __restrict__ bias, float* __restrict__ C)
{
    extern __shared__ float smf[];
    const uint32_t sb = smem_u32(smf);

    const int tid = threadIdx.x;
    const int bn = blockIdx.x * GBN;
    const int bm = blockIdx.y * GBM;

    const int w    = tid >> 5;
    const int wm   = w & 1;
    const int wn   = w >> 1;
    const int lane = tid & 31;
    const int g    = lane >> 2;
    const int t    = lane & 3;

    const int s  = tid & 7;
    const int r0 = tid >> 3;

    const uint32_t AsU[2] = { sb,                  sb + TILE_F * 4 };
    const uint32_t BsU[2] = { sb + 2 * TILE_F * 4, sb + 3 * TILE_F * 4 };

    const float* Ap = A  + (size_t)bm * EMB;
    const float* Bp = WT + (size_t)bn * EMB;

    float c[4][4][4];
#pragma unroll
    for (int mi = 0; mi < 4; ++mi)
#pragma unroll
        for (int ni = 0; ni < 4; ++ni)
#pragma unroll
            for (int j = 0; j < 4; ++j) c[mi][ni][j] = 0.f;

    const uint32_t dOffA = (uint32_t)((r0 * RSTR + s * 4) * 4);
    const size_t   gOffA = (size_t)r0 * EMB + s * 4;

    {
#pragma unroll
        for (int p = 0; p < 4; ++p) {
            CP_ASYNC16(AsU[0] + dOffA + (uint32_t)(32 * p * RSTR * 4),
                       Ap + gOffA + (size_t)32 * p * EMB);
            CP_ASYNC16(BsU[0] + dOffA + (uint32_t)(32 * p * RSTR * 4),
                       Bp + gOffA + (size_t)32 * p * EMB);
        }
        CP_COMMIT();
    }

    const int NKT = EMB / GBK;   // 32
    for (int kt = 0; kt < NKT; ++kt) {
        const int b = kt & 1;

        if (kt + 1 < NKT) {
            const int nb = b ^ 1;
            const size_t k0 = (size_t)(kt + 1) * GBK;
#pragma unroll
            for (int p = 0; p < 4; ++p) {
                CP_ASYNC16(AsU[nb] + dOffA + (uint32_t)(32 * p * RSTR * 4),
                           Ap + gOffA + k0 + (size_t)32 * p * EMB);
                CP_ASYNC16(BsU[nb] + dOffA + (uint32_t)(32 * p * RSTR * 4),
                           Bp + gOffA + k0 + (size_t)32 * p * EMB);
            }
            CP_COMMIT();
            asm volatile("cp.async.wait_group 1;" ::: "memory");
        } else {
            CP_WAIT0();
        }
        __syncthreads();

        const uint32_t aU = AsU[b];
        const uint32_t bU = BsU[b];
#pragma unroll
        for (int ks = 0; ks < 4; ++ks) {
            uint32_t af[4][4], bf[4][2];
#pragma unroll
            for (int mi = 0; mi < 4; ++mi) {
                uint32_t addr0 = aU + (uint32_t)(((wm * 64 + mi * 16 + g) * RSTR
                                                 + ks * 8 + 2 * t) * 4);
                LDS_V2(af[mi][0], af[mi][2], addr0);
                LDS_V2(af[mi][1], af[mi][3], addr0 + 8 * RSTR * 4);
            }
#pragma unroll
            for (int ni = 0; ni < 4; ++ni) {
                uint32_t addr = bU + (uint32_t)(((wn * 32 + ni * 8 + g) * RSTR
                                                + ks * 8 + 2 * t) * 4);
                LDS_V2(bf[ni][0], bf[ni][1], addr);
            }
#pragma unroll
            for (int mi = 0; mi < 4; ++mi)
#pragma unroll
                for (int ni = 0; ni < 4; ++ni)
                    MMA_TF32(c[mi][ni], af[mi], bf[ni]);
        }
        __syncthreads();
    }

    // ---- epilogue ----
    const int colb = bn + wn * 32;
    float2 bj[4];
#pragma unroll
    for (int ni = 0; ni < 4; ++ni) {
        bj[ni].x = bias[colb + ni * 8 + 2 * t];
        bj[ni].y = bias[colb + ni * 8 + 2 * t + 1];
    }

    if (MODE == 0) {
#pragma unroll
        for (int mi = 0; mi < 4; ++mi) {
            const size_t row0 = (size_t)(bm + wm * 64 + mi * 16 + g);
            const size_t row1 = row0 + 8;
#pragma unroll
            for (int ni = 0; ni < 4; ++ni) {
                const int col = colb + ni * 8 + 2 * t;
                float2 o0, o1;
                o0.x = c[mi][ni][0] + bj[ni].x;
                o0.y = c[mi][ni][1] + bj[ni].y;
                o1.x = c[mi][ni][2] + bj[ni].x;
                o1.y = c[mi][ni][3] + bj[ni].y;
                *(float2*)&C[row0 * EMB + col] = o0;
                *(float2*)&C[row1 * EMB + col] = o1;
            }
        }
    } else if (MODE == 1 || MODE == 2) {
        const int pc0 = perm8(2 * t);
        const int pc1 = perm8(2 * t + 1);
        const float sc = (MODE == 1) ? QSCALE : 1.f;
#pragma unroll
        for (int mi = 0; mi < 4; ++mi) {
            const size_t row0 = (size_t)(bm + wm * 64 + mi * 16 + g);
            const size_t row1 = row0 + 8;
#pragma unroll
            for (int ni = 0; ni < 4; ++ni) {
                const int nb8 = colb + ni * 8;
                C[row0 * EMB + nb8 + pc0] = tf32r((c[mi][ni][0] + bj[ni].x) * sc);
                C[row0 * EMB + nb8 + pc1] = tf32r((c[mi][ni][1] + bj[ni].y) * sc);
                C[row1 * EMB + nb8 + pc0] = tf32r((c[mi][ni][2] + bj[ni].x) * sc);
                C[row1 * EMB + nb8 + pc1] = tf32r((c[mi][ni][3] + bj[ni].y) * sc);
            }
        }
    } else {   // MODE 3: transposed V
#pragma unroll
        for (int mi = 0; mi < 4; ++mi) {
            const int m0 = bm + wm * 64 + mi * 16 + g;
            const int pm0 = (m0 & ~7) | perm8(m0 & 7);
            const int pm1 = pm0 + 8;
#pragma unroll
            for (int ni = 0; ni < 4; ++ni) {
                const size_t n0 = (size_t)(colb + ni * 8 + 2 * t);
                const size_t n1 = n0 + 1;
                C[n0 * MROWS + pm0] = tf32r(c[mi][ni][0] + bj[ni].x);
                C[n1 * MROWS + pm0] = tf32r(c[mi][ni][1] + bj[ni].y);
                C[n0 * MROWS + pm1] = tf32r(c[mi][ni][2] + bj[ni].x);
                C[n1 * MROWS + pm1] = tf32r(c[mi][ni][3] + bj[ni].y);
            }
        }
    }
}

// ============================================================================
// Flash attention, warp-owns-rows layout (8 warps x 16 query rows), no-max
// softmax, Q fragments hoisted to registers, P overlaid on Q smem (warp-
// private rows), double-buffered cp.async K/V. 2 CTAs/SM.
// ============================================================================
#define ATT_RST 72
#define ATT_VST 68
#define AOFF_QP 0                              // [128][72], Q then P
#define AOFF_K  (128 * ATT_RST)                // 2 x [64][72]
#define AOFF_V  (AOFF_K + 2 * 64 * ATT_RST)    // 2 x [64][68]
#define ATT_SMEM ((AOFF_V + 2 * 64 * ATT_VST) * 4)   // 108,544 B

__global__ void __launch_bounds__(256, 2)
attn_mma_kernel(const float* __restrict__ Q, const float* __restrict__ K,
                const float* __restrict__ VT, float* __restrict__ O)
{
    extern __shared__ float smf[];
    const uint32_t sb = smem_u32(smf);

    float* QPs = smf + AOFF_QP;
    const uint32_t QPsU = sb + AOFF_QP * 4;
    const uint32_t KsU[2] = { sb + AOFF_K * 4,
                              sb + (AOFF_K + 64 * ATT_RST) * 4 };
    const uint32_t VsU[2] = { sb + AOFF_V * 4,
                              sb + (AOFF_V + 64 * ATT_VST) * 4 };

    const int tid = threadIdx.x;
    const int qt = blockIdx.x;           // 0..15
    const int bh = blockIdx.y;           // 0..31
    const int b  = bh >> 4;
    const int hd = bh & 15;
    const int q0 = qt * 128;

    const float* Qg  = Q  + (size_t)b * SEQ * EMB + hd * HDIM;
    const float* Kg  = K  + (size_t)b * SEQ * EMB + hd * HDIM;
    const float* VTg = VT + (size_t)(hd * HDIM) * MROWS + b * SEQ;

    const int w    = tid >> 5;      // 0..7 : rows 16w..16w+15
    const int lane = tid & 31;
    const int g    = lane >> 2;
    const int t    = lane & 3;
    const int rowg = 16 * w + g;

    const int c4 = tid & 15;        // float4 chunk in 64-wide row
    const int rq = tid >> 4;        // 0..15

    // ---- stage Q (float4), K0/V0 (cp.async) ----
#pragma unroll
    for (int p = 0; p < 8; ++p) {
        int r = rq + 16 * p;
        *(float4*)&QPs[r * ATT_RST + c4 * 4] =
            *(const float4*)&Qg[(size_t)(q0 + r) * EMB + c4 * 4];
    }
#pragma unroll
    for (int p = 0; p < 4; ++p) {
        int r = rq + 16 * p;
        CP_ASYNC16(KsU[0] + (uint32_t)((r * ATT_RST + c4 * 4) * 4),
                   Kg + (size_t)r * EMB + c4 * 4);
        CP_ASYNC16(VsU[0] + (uint32_t)((r * ATT_VST + c4 * 4) * 4),
                   VTg + (size_t)r * MROWS + c4 * 4);
    }
    CP_COMMIT();
    __syncthreads();

    // ---- hoist Q fragments to registers (warp reads only its own rows) ----
    uint32_t qf[8][4];
    const uint32_t aQbase = QPsU + (uint32_t)((rowg * ATT_RST + 2 * t) * 4);
#pragma unroll
    for (int ks = 0; ks < 8; ++ks) {
        LDS_V2(qf[ks][0], qf[ks][2], aQbase + (uint32_t)(ks * 8 * 4));
        LDS_V2(qf[ks][1], qf[ks][3],
               aQbase + (uint32_t)(ks * 8 * 4) + 8 * ATT_RST * 4);
    }

    float o[8][4];
#pragma unroll
    for (int ni = 0; ni < 8; ++ni)
#pragma unroll
        for (int j = 0; j < 4; ++j) o[ni][j] = 0.f;
    float lp0 = 0.f, lp1 = 0.f;

    const int pos0 = perm8(2 * t);
    const int pos1 = perm8(2 * t + 1);
    float* prow0 = QPs + rowg * ATT_RST;   // P overlays Q (own rows only)
    float* prow1 = prow0 + 8 * ATT_RST;
    const uint32_t aPbase = aQbase;

    const int NT = SEQ / 64;   // 32
    for (int kt = 0; kt < NT; ++kt) {
        const int cur = kt & 1;

        CP_WAIT0();
        __syncthreads();   // buf[cur] ready; all warps done reading buf[cur^1]

        if (kt + 1 < NT) {
            const int nxt = cur ^ 1;
            const int k0n = (kt + 1) * 64;
#pragma unroll
            for (int p = 0; p < 4; ++p) {
                int r = rq + 16 * p;
                CP_ASYNC16(KsU[nxt] + (uint32_t)((r * ATT_RST + c4 * 4) * 4),
                           Kg + (size_t)(k0n + r) * EMB + c4 * 4);
                CP_ASYNC16(VsU[nxt] + (uint32_t)((r * ATT_VST + c4 * 4) * 4),
                           VTg + (size_t)r * MROWS + k0n + c4 * 4);
            }
            CP_COMMIT();
        }

        // ---- S = Q @ K^T  (warp tile 16 x 64; Q from registers) ----
        float s[8][4];
#pragma unroll
        for (int ni = 0; ni < 8; ++ni)
#pragma unroll
            for (int j = 0; j < 4; ++j) s[ni][j] = 0.f;

#pragma unroll
        for (int ks = 0; ks < 8; ++ks) {
#pragma unroll
            for (int ni = 0; ni < 8; ++ni) {
                uint32_t bf[2];
                LDS_V2(bf[0], bf[1],
                       KsU[cur] + (uint32_t)(((ni * 8 + g) * ATT_RST
                                              + ks * 8 + 2 * t) * 4));
                MMA_TF32(s[ni], qf[ks], bf);
            }
        }

        // ---- p = exp2(s); partial l; write P (own rows, permuted) ----
#pragma unroll
        for (int ni = 0; ni < 8; ++ni) {
            float r00 = tf32r(ex2(s[ni][0]));
            float r01 = tf32r(ex2(s[ni][1]));
            float r10 = tf32r(ex2(s[ni][2]));
            float r11 = tf32r(ex2(s[ni][3]));
            lp0 += r00 + r01;
            lp1 += r10 + r11;
            prow0[ni * 8 + pos0] = r00;
            prow0[ni * 8 + pos1] = r01;
            prow1[ni * 8 + pos0] = r10;
            prow1[ni * 8 + pos1] = r11;
        }
        __syncwarp();

        // ---- O += P @ Vt ----
#pragma unroll
        for (int ks = 0; ks < 8; ++ks) {
            uint32_t af[4];
            LDS_V2(af[0], af[2], aPbase + (uint32_t)(ks * 8 * 4));
            LDS_V2(af[1], af[3],
                   aPbase + (uint32_t)(ks * 8 * 4) + 8 * ATT_RST * 4);
#pragma unroll
            for (int ni = 0; ni < 8; ++ni) {
                uint32_t bf[2];
                LDS_V2(bf[0], bf[1],
                       VsU[cur] + (uint32_t)(((ni * 8 + g) * ATT_VST
                                              + ks * 8 + 2 * t) * 4));
                MMA_TF32(o[ni], af, bf);
            }
        }
    }

    // ---- epilogue: reduce l over t-lanes, normalize, store rounded+permuted ----
    lp0 += __shfl_xor_sync(0xffffffffu, lp0, 1);
    lp0 += __shfl_xor_sync(0xffffffffu, lp0, 2);
    lp1 += __shfl_xor_sync(0xffffffffu, lp1, 1);
    lp1 += __shfl_xor_sync(0xffffffffu, lp1, 2);
    const float inv0 = 1.f / lp0;
    const float inv1 = 1.f / lp1;

    const size_t grow0 = (size_t)(b * SEQ + q0 + rowg) * EMB + hd * HDIM;
    const size_t grow1 = grow0 + (size_t)8 * EMB;
#pragma unroll
    for (int ni = 0; ni < 8; ++ni) {
        O[grow0 + ni * 8 + pos0] = tf32r(o[ni][0] * inv0);
        O[grow0 + ni * 8 + pos1] = tf32r(o[ni][1] * inv0);
        O[grow1 + ni * 8 + pos0] = tf32r(o[ni][2] * inv1);
        O[grow1 + ni * 8 + pos1] = tf32r(o[ni][3] * inv1);
    }
}

// ============================================================================
// launch
// ============================================================================
extern "C" void kernel_launch(void* const* d_in, const int* in_sizes, int n_in,
                              void* d_out, int out_size)
{
    const float* xv = (const float*)d_in[0];
    const float* xk = (const float*)d_in[1];
    const float* xq = (const float*)d_in[2];
    const float* Wq = (const float*)d_in[3];
    const float* bq = (const float*)d_in[4];
    const float* Wk = (const float*)d_in[5];
    const float* bk = (const float*)d_in[6];
    const float* Wv = (const float*)d_in[7];
    const float* bv = (const float*)d_in[8];
    const float* Wo = (const float*)d_in[9];
    const float* bo = (const float*)d_in[10];
    float* out = (float*)d_out;

    float *Qd, *Kd, *VTd, *Cd, *WTd, *Xd;
    cudaGetSymbolAddress((void**)&Qd, g_Q);
    cudaGetSymbolAddress((void**)&Kd, g_K);
    cudaGetSymbolAddress((void**)&VTd, g_VT);
    cudaGetSymbolAddress((void**)&Cd, g_C);
    cudaGetSymbolAddress((void**)&WTd, g_WT);
    cudaGetSymbolAddress((void**)&Xd, g_X);

    float* WqT = WTd + 0ll * EMB * EMB;
    float* WkT = WTd + 1ll * EMB * EMB;
    float* WvT = WTd + 2ll * EMB * EMB;
    float* WoT = WTd + 3ll * EMB * EMB;
    float* Xq = Xd + 0ll * MROWS * EMB;
    float* Xk = Xd + 1ll * MROWS * EMB;
    float* Xv = Xd + 2ll * MROWS * EMB;

    const int prgrid = (MROWS * EMB / 8) / 256;   // 2048
    preround_perm_kernel<<<prgrid, 256>>>(xq, Xq);
    preround_perm_kernel<<<prgrid, 256>>>(xk, Xk);
    preround_perm_kernel<<<prgrid, 256>>>(xv, Xv);

    dim3 tgrid(EMB / 32, EMB / 32);
    dim3 tblk(32, 8);
    transpose_rna_kernel<<<tgrid, tblk>>>(Wq, WqT);
    transpose_rna_kernel<<<tgrid, tblk>>>(Wk, WkT);
    transpose_rna_kernel<<<tgrid, tblk>>>(Wv, WvT);
    transpose_rna_kernel<<<tgrid, tblk>>>(Wo, WoT);

    cudaFuncSetAttribute(gemm_tf32_kernel<0>,
                         cudaFuncAttributeMaxDynamicSharedMemorySize, GSMEM_TOTAL);
    cudaFuncSetAttribute(gemm_tf32_kernel<1>,
                         cudaFuncAttributeMaxDynamicSharedMemorySize, GSMEM_TOTAL);
    cudaFuncSetAttribute(gemm_tf32_kernel<2>,
                         cudaFuncAttributeMaxDynamicSharedMemorySize, GSMEM_TOTAL);
    cudaFuncSetAttribute(gemm_tf32_kernel<3>,
                         cudaFuncAttributeMaxDynamicSharedMemorySize, GSMEM_TOTAL);

    dim3 ggrid(EMB / GBN, MROWS / GBM);   // (8, 32)
    gemm_tf32_kernel<1><<<ggrid, 256, GSMEM_TOTAL>>>(Xq, WqT, bq, Qd);
    gemm_tf32_kernel<2><<<ggrid, 256, GSMEM_TOTAL>>>(Xk, WkT, bk, Kd);
    gemm_tf32_kernel<3><<<ggrid, 256, GSMEM_TOTAL>>>(Xv, WvT, bv, VTd);

    cudaFuncSetAttribute(attn_mma_kernel,
                         cudaFuncAttributeMaxDynamicSharedMemorySize, ATT_SMEM);
    dim3 agrid(SEQ / 128, BATCH * HEADS);  // (16, 32)
    attn_mma_kernel<<<agrid, 256, ATT_SMEM>>>(Qd, Kd, VTd, Cd);

    gemm_tf32_kernel<0><<<ggrid, 256, GSMEM_TOTAL>>>(Cd, WoT, bo, out);
}

// round 11
// speedup vs baseline: 2.0406x; 2.0406x over previous
#include <cuda_runtime.h>
#include <cuda_fp16.h>
#include <cstdint>
#include <math.h>

// Problem constants
#define BATCH 2
#define SEQ   2048
#define EMB   1024
#define HEADS 16
#define HDIM  64
#define MROWS (BATCH * SEQ)   // 4096

// ---------------- scratch (device globals; no allocations allowed) ---------
__device__ __half g_Q[MROWS * EMB];     // Q proj: scaled, rounded, pair-permuted dims
__device__ __half g_K[MROWS * EMB];     // K proj: rounded, pair-permuted dims
__device__ __half g_V[MROWS * EMB];     // V proj: rounded, plain [token][dim]
__device__ __half g_C[MROWS * EMB];     // attention out: rounded, pair-permuted dims
__device__ __half g_WT[4][EMB * EMB];   // W^T: rounded, pair-permuted k
__device__ __half g_X[3][MROWS * EMB];  // xq/xk/xv: rounded, pair-permuted k

#define QSCALE 0.18033688f   // 0.125 * log2(e)

// ============================================================================
// helpers
// ============================================================================
__device__ __forceinline__ uint32_t smem_u32(const void* p) {
    uint32_t a;
    asm("{ .reg .u64 t; cvta.to.shared.u64 t, %1; cvt.u32.u64 %0, t; }"
        : "=r"(a) : "l"(p));
    return a;
}

// pack two f32 -> f16x2 (lo = first arg)
__device__ __forceinline__ uint32_t h2pack(float lo, float hi) {
    uint32_t r;
    asm("cvt.rn.f16x2.f32 %0, %1, %2;" : "=r"(r) : "f"(hi), "f"(lo));
    return r;
}

__device__ __forceinline__ float ex2(float x) {
    float r;
    asm("ex2.approx.f32 %0, %1;" : "=f"(r) : "f"(x));
    return r;
}

#define MMA_F16(c, a, b)                                                      \
    asm volatile("mma.sync.aligned.m16n8k16.row.col.f32.f16.f16.f32 "         \
                 "{%0,%1,%2,%3}, {%4,%5,%6,%7}, {%8,%9}, {%0,%1,%2,%3};"      \
                 : "+f"((c)[0]), "+f"((c)[1]), "+f"((c)[2]), "+f"((c)[3])     \
                 : "r"((a)[0]), "r"((a)[1]), "r"((a)[2]), "r"((a)[3]),        \
                   "r"((b)[0]), "r"((b)[1]))

#define LDS_V2(r0, r1, addr)                                                  \
    asm volatile("ld.shared.v2.b32 {%0,%1}, [%2];"                            \
                 : "=r"(r0), "=r"(r1) : "r"(addr))

#define STS_V2(addr, r0, r1)                                                  \
    asm volatile("st.shared.v2.b32 [%0], {%1,%2};"                            \
                 :: "r"(addr), "r"(r0), "r"(r1) : "memory")

#define LDSM_X4_T(r0, r1, r2, r3, addr)                                       \
    asm volatile("ldmatrix.sync.aligned.m8n8.x4.trans.shared.b16 "            \
                 "{%0,%1,%2,%3}, [%4];"                                       \
                 : "=r"(r0), "=r"(r1), "=r"(r2), "=r"(r3) : "r"(addr))

#define CP_ASYNC16(dst, src)                                                  \
    asm volatile("cp.async.cg.shared.global [%0], [%1], 16;"                  \
                 :: "r"(dst), "l"(src))
#define CP_COMMIT() asm volatile("cp.async.commit_group;" ::: "memory")
#define CP_WAIT0()  asm volatile("cp.async.wait_group 0;" ::: "memory")

// pair-index permutation within a 16-half (8-pair) group
__device__ __forceinline__ int perm8(int p) {
    return ((p & 3) << 1) | (p >> 2);
}

// ============================================================================
// Pre-round to fp16 + pair-permute per 16-half group.
// ============================================================================
__global__ void __launch_bounds__(256)
preround_h16_kernel(const float* __restrict__ X, __half* __restrict__ Y)
{
    size_t i16 = (size_t)blockIdx.x * 256 + threadIdx.x;
    const float* xp = X + i16 * 16;
    uint32_t* yp = (uint32_t*)Y + i16 * 8;
    float x[16];
#pragma unroll
    for (int q = 0; q < 4; ++q) {
        float4 v = *(const float4*)&xp[q * 4];
        x[q * 4 + 0] = v.x; x[q * 4 + 1] = v.y;
        x[q * 4 + 2] = v.z; x[q * 4 + 3] = v.w;
    }
    uint32_t o[8];
#pragma unroll
    for (int p = 0; p < 8; ++p)
        o[perm8(p)] = h2pack(x[2 * p], x[2 * p + 1]);
    uint4 w0 = { o[0], o[1], o[2], o[3] };
    uint4 w1 = { o[4], o[5], o[6], o[7] };
    *(uint4*)&yp[0] = w0;
    *(uint4*)&yp[4] = w1;
}

// ============================================================================
// Weight transpose + fp16 round + pair-permute: WT[n][perm16(k)] = h(W[k][n])
// ============================================================================
__global__ void __launch_bounds__(256)
transpose_h_kernel(const float* __restrict__ W, __half* __restrict__ WT)
{
    __shared__ float tile[32][33];
    int x = blockIdx.x * 32 + threadIdx.x;   // n
    int y = blockIdx.y * 32 + threadIdx.y;   // k
#pragma unroll
    for (int j = 0; j < 32; j += 8)
        tile[threadIdx.y + j][threadIdx.x] = W[(size_t)(y + j) * EMB + x];
    __syncthreads();
    const int cu = threadIdx.x & 15;                 // k-pair within 32-k block
    const int nl0 = threadIdx.y + 8 * (threadIdx.x >> 4);
    uint32_t* Wu = (uint32_t*)WT;
#pragma unroll
    for (int j = 0; j < 32; j += 16) {
        int nl = nl0 + j;
        uint32_t h = h2pack(tile[2 * cu][nl], tile[2 * cu + 1][nl]);
        size_t n = (size_t)(blockIdx.x * 32 + nl);
        // group = blockIdx.y*2 + (cu>>3); u32 index = group*8 + perm8(cu&7)
        Wu[n * (EMB / 2) + blockIdx.y * 16 + (cu >> 3) * 8 + perm8(cu & 7)] = h;
    }
}

// ============================================================================
// fp16 mma.sync GEMM: C = A @ WT^T + bias. A/WT half, pair-permuted k.
// Tile 128x128, BK=64 halves (32 u32), NKT=16, double-buffered cp.async.
// MODE 0: fp32 row-major out | 1: Q (scaled, h2, perm) | 2: K (h2, perm)
// MODE 3: V (h2, plain [token][dim])
// ============================================================================
#define GBM 128
#define GBN 128
#define RSTR 40                      // u32 per row (32 data + 8 pad)
#define TILE_U (128 * RSTR)
#define GSMEM_TOTAL (4 * TILE_U * 4)

template <int MODE>
__global__ void __launch_bounds__(256, 2)
gemm_h_kernel(const __half* __restrict__ A, const __half* __restrict__ WT,
              const float* __restrict__ bias, void* __restrict__ Cv)
{
    extern __shared__ uint32_t smu[];
    const uint32_t sb = smem_u32(smu);

    const int tid = threadIdx.x;
    const int bn = blockIdx.x * GBN;
    const int bm = blockIdx.y * GBM;

    const int w    = tid >> 5;
    const int wm   = w & 1;
    const int wn   = w >> 1;
    const int lane = tid & 31;
    const int g    = lane >> 2;
    const int t    = lane & 3;

    const int s  = tid & 7;          // 16B chunk (4 u32) within 32-u32 row
    const int r0 = tid >> 3;         // 0..31

    const uint32_t AsU[2] = { sb,                  sb + TILE_U * 4 };
    const uint32_t BsU[2] = { sb + 2 * TILE_U * 4, sb + 3 * TILE_U * 4 };

    const __half* Ap = A  + (size_t)bm * EMB;
    const __half* Bp = WT + (size_t)bn * EMB;

    float c[4][4][4];
#pragma unroll
    for (int mi = 0; mi < 4; ++mi)
#pragma unroll
        for (int ni = 0; ni < 4; ++ni)
#pragma unroll
            for (int j = 0; j < 4; ++j) c[mi][ni][j] = 0.f;

    const uint32_t dOff = (uint32_t)((r0 * RSTR + s * 4) * 4);
    const size_t   gOff = (size_t)r0 * EMB + s * 8;   // halves

    {
#pragma unroll
        for (int p = 0; p < 4; ++p) {
            CP_ASYNC16(AsU[0] + dOff + (uint32_t)(32 * p * RSTR * 4),
                       Ap + gOff + (size_t)32 * p * EMB);
            CP_ASYNC16(BsU[0] + dOff + (uint32_t)(32 * p * RSTR * 4),
                       Bp + gOff + (size_t)32 * p * EMB);
        }
        CP_COMMIT();
    }

    const int NKT = EMB / 64;   // 16
    for (int kt = 0; kt < NKT; ++kt) {
        const int b = kt & 1;

        if (kt + 1 < NKT) {
            const int nb = b ^ 1;
            const size_t k0 = (size_t)(kt + 1) * 64;   // halves
#pragma unroll
            for (int p = 0; p < 4; ++p) {
                CP_ASYNC16(AsU[nb] + dOff + (uint32_t)(32 * p * RSTR * 4),
                           Ap + gOff + k0 + (size_t)32 * p * EMB);
                CP_ASYNC16(BsU[nb] + dOff + (uint32_t)(32 * p * RSTR * 4),
                           Bp + gOff + k0 + (size_t)32 * p * EMB);
            }
            CP_COMMIT();
            asm volatile("cp.async.wait_group 1;" ::: "memory");
        } else {
            CP_WAIT0();
        }
        __syncthreads();

        const uint32_t aU = AsU[b];
        const uint32_t bU = BsU[b];
#pragma unroll
        for (int ks = 0; ks < 4; ++ks) {       // each kstep = 16 halves
            uint32_t af[4][4], bf[4][2];
#pragma unroll
            for (int mi = 0; mi < 4; ++mi) {
                uint32_t addr0 = aU + (uint32_t)(((wm * 64 + mi * 16 + g) * RSTR
                                                 + ks * 8 + 2 * t) * 4);
                LDS_V2(af[mi][0], af[mi][2], addr0);
                LDS_V2(af[mi][1], af[mi][3], addr0 + 8 * RSTR * 4);
            }
#pragma unroll
            for (int ni = 0; ni < 4; ++ni) {
                uint32_t addr = bU + (uint32_t)(((wn * 32 + ni * 8 + g) * RSTR
                                                + ks * 8 + 2 * t) * 4);
                LDS_V2(bf[ni][0], bf[ni][1], addr);
            }
#pragma unroll
            for (int mi = 0; mi < 4; ++mi)
#pragma unroll
                for (int ni = 0; ni < 4; ++ni)
                    MMA_F16(c[mi][ni], af[mi], bf[ni]);
        }
        __syncthreads();
    }

    // ---- epilogue ----
    const int colb = bn + wn * 32;
    float2 bj[4];
#pragma unroll
    for (int ni = 0; ni < 4; ++ni) {
        bj[ni].x = bias[colb + ni * 8 + 2 * t];
        bj[ni].y = bias[colb + ni * 8 + 2 * t + 1];
    }

    if (MODE == 0) {
        float* C = (float*)Cv;
#pragma unroll
        for (int mi = 0; mi < 4; ++mi) {
            const size_t row0 = (size_t)(bm + wm * 64 + mi * 16 + g);
            const size_t row1 = row0 + 8;
#pragma unroll
            for (int ni = 0; ni < 4; ++ni) {
                const int col = colb + ni * 8 + 2 * t;
                float2 o0, o1;
                o0.x = c[mi][ni][0] + bj[ni].x;
                o0.y = c[mi][ni][1] + bj[ni].y;
                o1.x = c[mi][ni][2] + bj[ni].x;
                o1.y = c[mi][ni][3] + bj[ni].y;
                *(float2*)&C[row0 * EMB + col] = o0;
                *(float2*)&C[row1 * EMB + col] = o1;
            }
        }
    } else if (MODE == 1 || MODE == 2) {
        uint32_t* Cu = (uint32_t*)Cv;
        const float sc = (MODE == 1) ? QSCALE : 1.f;
#pragma unroll
        for (int mi = 0; mi < 4; ++mi) {
            const size_t row0 = (size_t)(bm + wm * 64 + mi * 16 + g);
            const size_t row1 = row0 + 8;
#pragma unroll
            for (int ni = 0; ni < 4; ++ni) {
                const int grp = colb / 16 + (ni >> 1);
                const int pos = grp * 8 + perm8((ni & 1) * 4 + t);
                Cu[row0 * (EMB / 2) + pos] =
                    h2pack((c[mi][ni][0] + bj[ni].x) * sc,
                           (c[mi][ni][1] + bj[ni].y) * sc);
                Cu[row1 * (EMB / 2) + pos] =
                    h2pack((c[mi][ni][2] + bj[ni].x) * sc,
                           (c[mi][ni][3] + bj[ni].y) * sc);
            }
        }
    } else {   // MODE 3: V plain [token][dim] half
        uint32_t* Cu = (uint32_t*)Cv;
#pragma unroll
        for (int mi = 0; mi < 4; ++mi) {
            const size_t row0 = (size_t)(bm + wm * 64 + mi * 16 + g);
            const size_t row1 = row0 + 8;
#pragma unroll
            for (int ni = 0; ni < 4; ++ni) {
                const int posu = (colb >> 1) + ni * 4 + t;
                Cu[row0 * (EMB / 2) + posu] =
                    h2pack(c[mi][ni][0] + bj[ni].x, c[mi][ni][1] + bj[ni].y);
                Cu[row1 * (EMB / 2) + posu] =
                    h2pack(c[mi][ni][2] + bj[ni].x, c[mi][ni][3] + bj[ni].y);
            }
        }
    }
}

// ============================================================================
// Flash attention, fp16 m16n8k16, warp-owns-rows (8 warps x 16 q-rows),
// no-max softmax, Q fragments in regs, P overlaid on Q smem, cp.async
// double-buffered K/V, V via ldmatrix.trans. 2 CTAs/SM.
// Strides: QP/K rows = 40 u32 (v2-load conflict-free), V rows = 36 u32
// (ldmatrix conflict-free).
// ============================================================================
#define RSQP 40
#define RSK  40
#define RSV  36
#define AOFF_QP 0                              // [128][RSQP] u32 (Q then P)
#define AOFF_K  (128 * RSQP)                   // 2 x [64][RSK]
#define AOFF_V  (AOFF_K + 2 * 64 * RSK)        // 2 x [64][RSV]
#define ATT_SMEM ((AOFF_V + 2 * 64 * RSV) * 4) // 59,392 B -> 2 CTAs/SM

__global__ void __launch_bounds__(256, 2)
attn_mma_kernel(const __half* __restrict__ Q, const __half* __restrict__ K,
                const __half* __restrict__ V, __half* __restrict__ O)
{
    extern __shared__ uint32_t smu[];
    const uint32_t sb = smem_u32(smu);

    const uint32_t QPsU = sb + AOFF_QP * 4;
    const uint32_t KsU[2] = { sb + AOFF_K * 4, sb + (AOFF_K + 64 * RSK) * 4 };
    const uint32_t VsU[2] = { sb + AOFF_V * 4, sb + (AOFF_V + 64 * RSV) * 4 };

    const int tid = threadIdx.x;
    const int qt = blockIdx.x;           // 0..15
    const int bh = blockIdx.y;           // 0..31
    const int b  = bh >> 4;
    const int hd = bh & 15;
    const int q0 = qt * 128;

    const __half* Qg = Q + (size_t)(b * SEQ + q0) * EMB + hd * HDIM;
    const __half* Kg = K + (size_t)b * SEQ * EMB + hd * HDIM;
    const __half* Vg = V + (size_t)b * SEQ * EMB + hd * HDIM;

    const int w    = tid >> 5;      // 0..7 : q-rows 16w..16w+15
    const int lane = tid & 31;
    const int g    = lane >> 2;
    const int t    = lane & 3;
    const int rowg = 16 * w + g;

    const int cq = tid & 7;         // 16B chunk within 64-half row
    const int rr = tid >> 3;        // 0..31

    // ---- stage Q (128 rows), K0/V0 (64 rows each) via cp.async ----
#pragma unroll
    for (int p = 0; p < 4; ++p) {
        int r = rr + 32 * p;
        CP_ASYNC16(QPsU + (uint32_t)((r * RSQP + cq * 4) * 4),
                   Qg + (size_t)r * EMB + cq * 8);
    }
#pragma unroll
    for (int p = 0; p < 2; ++p) {
        int r = rr + 32 * p;
        CP_ASYNC16(KsU[0] + (uint32_t)((r * RSK + cq * 4) * 4),
                   Kg + (size_t)r * EMB + cq * 8);
        CP_ASYNC16(VsU[0] + (uint32_t)((r * RSV + cq * 4) * 4),
                   Vg + (size_t)r * EMB + cq * 8);
    }
    CP_COMMIT();
    CP_WAIT0();
    __syncthreads();

    // ---- hoist Q fragments (4 ksteps of 16 halves) ----
    uint32_t qf[4][4];
    const uint32_t aQbase = QPsU + (uint32_t)((rowg * RSQP + 2 * t) * 4);
#pragma unroll
    for (int ks = 0; ks < 4; ++ks) {
        LDS_V2(qf[ks][0], qf[ks][2], aQbase + (uint32_t)(ks * 8 * 4));
        LDS_V2(qf[ks][1], qf[ks][3],
               aQbase + (uint32_t)(ks * 8 * 4) + 8 * RSQP * 4);
    }

    float o[8][4];
#pragma unroll
    for (int ni = 0; ni < 8; ++ni)
#pragma unroll
        for (int j = 0; j < 4; ++j) o[ni][j] = 0.f;
    float lp0 = 0.f, lp1 = 0.f;

    // P row pointers (overlay on Q smem; warp-private rows)
    const uint32_t prow0 = QPsU + (uint32_t)((rowg * RSQP) * 4);
    const uint32_t prow1 = prow0 + (uint32_t)(8 * RSQP * 4);
    const uint32_t aPbase = aQbase;

    // ldmatrix per-lane base: row (lane&15), half-col 8*(lane>>4)
    const uint32_t vlane = (uint32_t)(((lane & 15) * RSV + 4 * (lane >> 4)) * 4);

    const int NT = SEQ / 64;   // 32
    for (int kt = 0; kt < NT; ++kt) {
        const int cur = kt & 1;

        CP_WAIT0();
        __syncthreads();

        if (kt + 1 < NT) {
            const int nxt = cur ^ 1;
            const int k0n = (kt + 1) * 64;
#pragma unroll
            for (int p = 0; p < 2; ++p) {
                int r = rr + 32 * p;
                CP_ASYNC16(KsU[nxt] + (uint32_t)((r * RSK + cq * 4) * 4),
                           Kg + (size_t)(k0n + r) * EMB + cq * 8);
                CP_ASYNC16(VsU[nxt] + (uint32_t)((r * RSV + cq * 4) * 4),
                           Vg + (size_t)(k0n + r) * EMB + cq * 8);
            }
            CP_COMMIT();
        }

        // ---- S = Q @ K^T (warp tile 16 x 64) ----
        float s[8][4];
#pragma unroll
        for (int ni = 0; ni < 8; ++ni)
#pragma unroll
            for (int j = 0; j < 4; ++j) s[ni][j] = 0.f;

#pragma unroll
        for (int ks = 0; ks < 4; ++ks) {
#pragma unroll
            for (int ni = 0; ni < 8; ++ni) {
                uint32_t bf[2];
                LDS_V2(bf[0], bf[1],
                       KsU[cur] + (uint32_t)(((ni * 8 + g) * RSK
                                              + ks * 8 + 2 * t) * 4));
                MMA_F16(s[ni], qf[ks], bf);
            }
        }

        // ---- p = exp2(s); partial l; write P (half2, pair-permuted) ----
#pragma unroll
        for (int j = 0; j < 4; ++j) {
            float p00 = ex2(s[2 * j][0]);
            float p01 = ex2(s[2 * j][1]);
            float p02 = ex2(s[2 * j][2]);
            float p03 = ex2(s[2 * j][3]);
            float p10 = ex2(s[2 * j + 1][0]);
            float p11 = ex2(s[2 * j + 1][1]);
            float p12 = ex2(s[2 * j + 1][2]);
            float p13 = ex2(s[2 * j + 1][3]);
            lp0 += p00 + p01 + p10 + p11;
            lp1 += p02 + p03 + p12 + p13;
            STS_V2(prow0 + (uint32_t)((j * 8 + 2 * t) * 4),
                   h2pack(p00, p01), h2pack(p10, p11));
            STS_V2(prow1 + (uint32_t)((j * 8 + 2 * t) * 4),
                   h2pack(p02, p03), h2pack(p12, p13));
        }
        __syncwarp();

        // ---- O += P @ V (V via ldmatrix.trans) ----
#pragma unroll
        for (int ks = 0; ks < 4; ++ks) {
            uint32_t af[4];
            LDS_V2(af[0], af[2], aPbase + (uint32_t)(ks * 8 * 4));
            LDS_V2(af[1], af[3],
                   aPbase + (uint32_t)(ks * 8 * 4) + 8 * RSQP * 4);
            const uint32_t vrow = VsU[cur] + vlane
                                + (uint32_t)(ks * 16 * RSV * 4);
#pragma unroll
            for (int d16 = 0; d16 < 4; ++d16) {
                uint32_t r0, r1, r2, r3;
                LDSM_X4_T(r0, r1, r2, r3, vrow + (uint32_t)(d16 * 8 * 4));
                uint32_t b0[2] = { r0, r1 };
                uint32_t b1[2] = { r2, r3 };
                MMA_F16(o[2 * d16],     af, b0);
                MMA_F16(o[2 * d16 + 1], af, b1);
            }
        }
    }

    // ---- reduce l over t-lanes, normalize, store half2 pair-permuted ----
    lp0 += __shfl_xor_sync(0xffffffffu, lp0, 1);
    lp0 += __shfl_xor_sync(0xffffffffu, lp0, 2);
    lp1 += __shfl_xor_sync(0xffffffffu, lp1, 1);
    lp1 += __shfl_xor_sync(0xffffffffu, lp1, 2);
    const float inv0 = 1.f / lp0;
    const float inv1 = 1.f / lp1;

    uint32_t* Ou = (uint32_t*)O;
    const size_t tok0 = (size_t)(b * SEQ + q0 + rowg);
    const size_t tok1 = tok0 + 8;
#pragma unroll
    for (int ni = 0; ni < 8; ++ni) {
        const int grp = hd * 4 + (ni >> 1);
        const int pos = grp * 8 + perm8((ni & 1) * 4 + t);
        Ou[tok0 * (EMB / 2) + pos] = h2pack(o[ni][0] * inv0, o[ni][1] * inv0);
        Ou[tok1 * (EMB / 2) + pos] = h2pack(o[ni][2] * inv1, o[ni][3] * inv1);
    }
}

// ============================================================================
// launch
// ============================================================================
extern "C" void kernel_launch(void* const* d_in, const int* in_sizes, int n_in,
                              void* d_out, int out_size)
{
    const float* xv = (const float*)d_in[0];
    const float* xk = (const float*)d_in[1];
    const float* xq = (const float*)d_in[2];
    const float* Wq = (const float*)d_in[3];
    const float* bq = (const float*)d_in[4];
    const float* Wk = (const float*)d_in[5];
    const float* bk = (const float*)d_in[6];
    const float* Wv = (const float*)d_in[7];
    const float* bv = (const float*)d_in[8];
    const float* Wo = (const float*)d_in[9];
    const float* bo = (const float*)d_in[10];
    float* out = (float*)d_out;

    __half *Qd, *Kd, *Vd, *Cd, *WTd, *Xd;
    cudaGetSymbolAddress((void**)&Qd, g_Q);
    cudaGetSymbolAddress((void**)&Kd, g_K);
    cudaGetSymbolAddress((void**)&Vd, g_V);
    cudaGetSymbolAddress((void**)&Cd, g_C);
    cudaGetSymbolAddress((void**)&WTd, g_WT);
    cudaGetSymbolAddress((void**)&Xd, g_X);

    __half* WqT = WTd + 0ll * EMB * EMB;
    __half* WkT = WTd + 1ll * EMB * EMB;
    __half* WvT = WTd + 2ll * EMB * EMB;
    __half* WoT = WTd + 3ll * EMB * EMB;
    __half* Xq = Xd + 0ll * MROWS * EMB;
    __half* Xk = Xd + 1ll * MROWS * EMB;
    __half* Xv = Xd + 2ll * MROWS * EMB;

    const int prgrid = (MROWS * EMB / 16) / 256;   // 1024
    preround_h16_kernel<<<prgrid, 256>>>(xq, Xq);
    preround_h16_kernel<<<prgrid, 256>>>(xk, Xk);
    preround_h16_kernel<<<prgrid, 256>>>(xv, Xv);

    dim3 tgrid(EMB / 32, EMB / 32);
    dim3 tblk(32, 8);
    transpose_h_kernel<<<tgrid, tblk>>>(Wq, WqT);
    transpose_h_kernel<<<tgrid, tblk>>>(Wk, WkT);
    transpose_h_kernel<<<tgrid, tblk>>>(Wv, WvT);
    transpose_h_kernel<<<tgrid, tblk>>>(Wo, WoT);

    cudaFuncSetAttribute(gemm_h_kernel<0>,
                         cudaFuncAttributeMaxDynamicSharedMemorySize, GSMEM_TOTAL);
    cudaFuncSetAttribute(gemm_h_kernel<1>,
                         cudaFuncAttributeMaxDynamicSharedMemorySize, GSMEM_TOTAL);
    cudaFuncSetAttribute(gemm_h_kernel<2>,
                         cudaFuncAttributeMaxDynamicSharedMemorySize, GSMEM_TOTAL);
    cudaFuncSetAttribute(gemm_h_kernel<3>,
                         cudaFuncAttributeMaxDynamicSharedMemorySize, GSMEM_TOTAL);

    dim3 ggrid(EMB / GBN, MROWS / GBM);   // (8, 32)
    gemm_h_kernel<1><<<ggrid, 256, GSMEM_TOTAL>>>(Xq, WqT, bq, Qd);
    gemm_h_kernel<2><<<ggrid, 256, GSMEM_TOTAL>>>(Xk, WkT, bk, Kd);
    gemm_h_kernel<3><<<ggrid, 256, GSMEM_TOTAL>>>(Xv, WvT, bv, Vd);

    cudaFuncSetAttribute(attn_mma_kernel,
                         cudaFuncAttributeMaxDynamicSharedMemorySize, ATT_SMEM);
    dim3 agrid(SEQ / 128, BATCH * HEADS);  // (16, 32)
    attn_mma_kernel<<<agrid, 256, ATT_SMEM>>>(Qd, Kd, Vd, Cd);

    gemm_h_kernel<0><<<ggrid, 256, GSMEM_TOTAL>>>(Cd, WoT, bo, out);
}

// round 12
// speedup vs baseline: 2.1604x; 1.0587x over previous
#include <cuda_runtime.h>
#include <cuda_fp16.h>
#include <cstdint>
#include <math.h>

// Problem constants
#define BATCH 2
#define SEQ   2048
#define EMB   1024
#define HEADS 16
#define HDIM  64
#define MROWS (BATCH * SEQ)   // 4096

// ---------------- scratch (device globals; no allocations allowed) ---------
__device__ __half g_Q[MROWS * EMB];     // Q proj: scaled, rounded, pair-permuted dims
__device__ __half g_K[MROWS * EMB];     // K proj: rounded, pair-permuted dims
__device__ __half g_V[MROWS * EMB];     // V proj: rounded, plain [token][dim]
__device__ __half g_C[MROWS * EMB];     // attention out: rounded, pair-permuted dims
__device__ __half g_WT[4][EMB * EMB];   // W^T: rounded, pair-permuted k
__device__ __half g_X[3][MROWS * EMB];  // xq/xk/xv: rounded, pair-permuted k

#define QSCALE 0.18033688f   // 0.125 * log2(e)

// ============================================================================
// helpers
// ============================================================================
__device__ __forceinline__ uint32_t smem_u32(const void* p) {
    uint32_t a;
    asm("{ .reg .u64 t; cvta.to.shared.u64 t, %1; cvt.u32.u64 %0, t; }"
        : "=r"(a) : "l"(p));
    return a;
}

// pack two f32 -> f16x2 (lo = first arg)
__device__ __forceinline__ uint32_t h2pack(float lo, float hi) {
    uint32_t r;
    asm("cvt.rn.f16x2.f32 %0, %1, %2;" : "=r"(r) : "f"(hi), "f"(lo));
    return r;
}

__device__ __forceinline__ float ex2(float x) {
    float r;
    asm("ex2.approx.f32 %0, %1;" : "=f"(r) : "f"(x));
    return r;
}

#define MMA_F16(c, a, b)                                                      \
    asm volatile("mma.sync.aligned.m16n8k16.row.col.f32.f16.f16.f32 "         \
                 "{%0,%1,%2,%3}, {%4,%5,%6,%7}, {%8,%9}, {%0,%1,%2,%3};"      \
                 : "+f"((c)[0]), "+f"((c)[1]), "+f"((c)[2]), "+f"((c)[3])     \
                 : "r"((a)[0]), "r"((a)[1]), "r"((a)[2]), "r"((a)[3]),        \
                   "r"((b)[0]), "r"((b)[1]))

#define LDS_V2(r0, r1, addr)                                                  \
    asm volatile("ld.shared.v2.b32 {%0,%1}, [%2];"                            \
                 : "=r"(r0), "=r"(r1) : "r"(addr))

#define STS_V2(addr, r0, r1)                                                  \
    asm volatile("st.shared.v2.b32 [%0], {%1,%2};"                            \
                 :: "r"(addr), "r"(r0), "r"(r1) : "memory")

#define LDSM_X4_T(r0, r1, r2, r3, addr)                                       \
    asm volatile("ldmatrix.sync.aligned.m8n8.x4.trans.shared.b16 "            \
                 "{%0,%1,%2,%3}, [%4];"                                       \
                 : "=r"(r0), "=r"(r1), "=r"(r2), "=r"(r3) : "r"(addr))

#define CP_ASYNC16(dst, src)                                                  \
    asm volatile("cp.async.cg.shared.global [%0], [%1], 16;"                  \
                 :: "r"(dst), "l"(src))
#define CP_COMMIT() asm volatile("cp.async.commit_group;" ::: "memory")
#define CP_WAIT0()  asm volatile("cp.async.wait_group 0;" ::: "memory")

// pair-index permutation within a 16-half (8-pair) group
__device__ __forceinline__ int perm8(int p) {
    return ((p & 3) << 1) | (p >> 2);
}

// ============================================================================
// Merged pre-round (xq/xk/xv) to fp16 + pair-permute per 16-half group.
// grid.y = 0/1/2 selects tensor.
// ============================================================================
__global__ void __launch_bounds__(256)
preround3_kernel(const float* __restrict__ xq, const float* __restrict__ xk,
                 const float* __restrict__ xv, __half* __restrict__ Ybase)
{
    const int z = blockIdx.y;
    const float* X = (z == 0) ? xq : (z == 1) ? xk : xv;
    __half* Y = Ybase + (size_t)z * MROWS * EMB;

    size_t i16 = (size_t)blockIdx.x * 256 + threadIdx.x;
    const float* xp = X + i16 * 16;
    uint32_t* yp = (uint32_t*)Y + i16 * 8;
    float x[16];
#pragma unroll
    for (int q = 0; q < 4; ++q) {
        float4 v = *(const float4*)&xp[q * 4];
        x[q * 4 + 0] = v.x; x[q * 4 + 1] = v.y;
        x[q * 4 + 2] = v.z; x[q * 4 + 3] = v.w;
    }
    uint32_t o[8];
#pragma unroll
    for (int p = 0; p < 8; ++p)
        o[perm8(p)] = h2pack(x[2 * p], x[2 * p + 1]);
    uint4 w0 = { o[0], o[1], o[2], o[3] };
    uint4 w1 = { o[4], o[5], o[6], o[7] };
    *(uint4*)&yp[0] = w0;
    *(uint4*)&yp[4] = w1;
}

// ============================================================================
// Merged weight transpose (4 weights) + fp16 round + pair-permute.
// grid.z = 0..3 selects weight. WT[n][perm16(k)] = h(W[k][n])
// ============================================================================
__global__ void __launch_bounds__(256)
transpose4_kernel(const float* __restrict__ Wq, const float* __restrict__ Wk,
                  const float* __restrict__ Wv, const float* __restrict__ Wo,
                  __half* __restrict__ WTbase)
{
    const int z = blockIdx.z;
    const float* W = (z == 0) ? Wq : (z == 1) ? Wk : (z == 2) ? Wv : Wo;
    __half* WT = WTbase + (size_t)z * EMB * EMB;

    __shared__ float tile[32][33];
    int x = blockIdx.x * 32 + threadIdx.x;   // n
    int y = blockIdx.y * 32 + threadIdx.y;   // k
#pragma unroll
    for (int j = 0; j < 32; j += 8)
        tile[threadIdx.y + j][threadIdx.x] = W[(size_t)(y + j) * EMB + x];
    __syncthreads();
    const int cu = threadIdx.x & 15;                 // k-pair within 32-k block
    const int nl0 = threadIdx.y + 8 * (threadIdx.x >> 4);
    uint32_t* Wu = (uint32_t*)WT;
#pragma unroll
    for (int j = 0; j < 32; j += 16) {
        int nl = nl0 + j;
        uint32_t h = h2pack(tile[2 * cu][nl], tile[2 * cu + 1][nl]);
        size_t n = (size_t)(blockIdx.x * 32 + nl);
        Wu[n * (EMB / 2) + blockIdx.y * 16 + (cu >> 3) * 8 + perm8(cu & 7)] = h;
    }
}

// ============================================================================
// fp16 mma.sync GEMM mainloop (shared by both GEMM kernels).
// Tile 128x128, BK=64 halves (32 u32), NKT=16, double-buffered cp.async.
// ============================================================================
#define GBM 128
#define GBN 128
#define RSTR 40                      // u32 per row (32 data + 8 pad)
#define TILE_U (128 * RSTR)
#define GSMEM_TOTAL (4 * TILE_U * 4)

struct GemmCtx {
    int wm, wn, g, t;
    float c[4][4][4];
};

__device__ __forceinline__ void gemm_mainloop(
    const __half* __restrict__ Ap, const __half* __restrict__ Bp,
    uint32_t sb, int tid, GemmCtx& ctx)
{
    const int w    = tid >> 5;
    ctx.wm = w & 1;
    ctx.wn = w >> 1;
    const int lane = tid & 31;
    ctx.g = lane >> 2;
    ctx.t = lane & 3;

    const int s  = tid & 7;
    const int r0 = tid >> 3;

    const uint32_t AsU[2] = { sb,                  sb + TILE_U * 4 };
    const uint32_t BsU[2] = { sb + 2 * TILE_U * 4, sb + 3 * TILE_U * 4 };

#pragma unroll
    for (int mi = 0; mi < 4; ++mi)
#pragma unroll
        for (int ni = 0; ni < 4; ++ni)
#pragma unroll
            for (int j = 0; j < 4; ++j) ctx.c[mi][ni][j] = 0.f;

    const uint32_t dOff = (uint32_t)((r0 * RSTR + s * 4) * 4);
    const size_t   gOff = (size_t)r0 * EMB + s * 8;   // halves

    {
#pragma unroll
        for (int p = 0; p < 4; ++p) {
            CP_ASYNC16(AsU[0] + dOff + (uint32_t)(32 * p * RSTR * 4),
                       Ap + gOff + (size_t)32 * p * EMB);
            CP_ASYNC16(BsU[0] + dOff + (uint32_t)(32 * p * RSTR * 4),
                       Bp + gOff + (size_t)32 * p * EMB);
        }
        CP_COMMIT();
    }

    const int NKT = EMB / 64;   // 16
    for (int kt = 0; kt < NKT; ++kt) {
        const int b = kt & 1;

        if (kt + 1 < NKT) {
            const int nb = b ^ 1;
            const size_t k0 = (size_t)(kt + 1) * 64;   // halves
#pragma unroll
            for (int p = 0; p < 4; ++p) {
                CP_ASYNC16(AsU[nb] + dOff + (uint32_t)(32 * p * RSTR * 4),
                           Ap + gOff + k0 + (size_t)32 * p * EMB);
                CP_ASYNC16(BsU[nb] + dOff + (uint32_t)(32 * p * RSTR * 4),
                           Bp + gOff + k0 + (size_t)32 * p * EMB);
            }
            CP_COMMIT();
            asm volatile("cp.async.wait_group 1;" ::: "memory");
        } else {
            CP_WAIT0();
        }
        __syncthreads();

        const uint32_t aU = AsU[b];
        const uint32_t bU = BsU[b];
#pragma unroll
        for (int ks = 0; ks < 4; ++ks) {       // each kstep = 16 halves
            uint32_t af[4][4], bf[4][2];
#pragma unroll
            for (int mi = 0; mi < 4; ++mi) {
                uint32_t addr0 = aU + (uint32_t)(((ctx.wm * 64 + mi * 16 + ctx.g) * RSTR
                                                 + ks * 8 + 2 * ctx.t) * 4);
                LDS_V2(af[mi][0], af[mi][2], addr0);
                LDS_V2(af[mi][1], af[mi][3], addr0 + 8 * RSTR * 4);
            }
#pragma unroll
            for (int ni = 0; ni < 4; ++ni) {
                uint32_t addr = bU + (uint32_t)(((ctx.wn * 32 + ni * 8 + ctx.g) * RSTR
                                                + ks * 8 + 2 * ctx.t) * 4);
                LDS_V2(bf[ni][0], bf[ni][1], addr);
            }
#pragma unroll
            for (int mi = 0; mi < 4; ++mi)
#pragma unroll
                for (int ni = 0; ni < 4; ++ni)
                    MMA_F16(ctx.c[mi][ni], af[mi], bf[ni]);
        }
        __syncthreads();
    }
}

// ============================================================================
// Merged QKV GEMM: grid.z = 0 (Q: scaled h2 perm), 1 (K: h2 perm),
// 2 (V: h2 plain [token][dim]).
// ============================================================================
__global__ void __launch_bounds__(256, 2)
gemm_qkv_kernel(const __half* __restrict__ Xbase, const __half* __restrict__ WTbase,
                const float* __restrict__ bq, const float* __restrict__ bk,
                const float* __restrict__ bv,
                __half* __restrict__ Qd, __half* __restrict__ Kd,
                __half* __restrict__ Vd)
{
    extern __shared__ uint32_t smu[];
    const uint32_t sb = smem_u32(smu);
    const int tid = threadIdx.x;
    const int bn = blockIdx.x * GBN;
    const int bm = blockIdx.y * GBM;
    const int z  = blockIdx.z;

    const __half* A  = Xbase  + (size_t)z * MROWS * EMB + (size_t)bm * EMB;
    const __half* Bw = WTbase + (size_t)z * EMB * EMB   + (size_t)bn * EMB;
    const float* bias = (z == 0) ? bq : (z == 1) ? bk : bv;
    __half* outp = (z == 0) ? Qd : (z == 1) ? Kd : Vd;

    GemmCtx ctx;
    gemm_mainloop(A, Bw, sb, tid, ctx);

    const int colb = bn + ctx.wn * 32;
    const int g = ctx.g, t = ctx.t;
    float2 bj[4];
#pragma unroll
    for (int ni = 0; ni < 4; ++ni) {
        bj[ni].x = bias[colb + ni * 8 + 2 * t];
        bj[ni].y = bias[colb + ni * 8 + 2 * t + 1];
    }

    uint32_t* Cu = (uint32_t*)outp;
    if (z < 2) {
        const float sc = (z == 0) ? QSCALE : 1.f;
#pragma unroll
        for (int mi = 0; mi < 4; ++mi) {
            const size_t row0 = (size_t)(bm + ctx.wm * 64 + mi * 16 + g);
            const size_t row1 = row0 + 8;
#pragma unroll
            for (int ni = 0; ni < 4; ++ni) {
                const int grp = colb / 16 + (ni >> 1);
                const int pos = grp * 8 + perm8((ni & 1) * 4 + t);
                Cu[row0 * (EMB / 2) + pos] =
                    h2pack((ctx.c[mi][ni][0] + bj[ni].x) * sc,
                           (ctx.c[mi][ni][1] + bj[ni].y) * sc);
                Cu[row1 * (EMB / 2) + pos] =
                    h2pack((ctx.c[mi][ni][2] + bj[ni].x) * sc,
                           (ctx.c[mi][ni][3] + bj[ni].y) * sc);
            }
        }
    } else {   // V plain [token][dim]
#pragma unroll
        for (int mi = 0; mi < 4; ++mi) {
            const size_t row0 = (size_t)(bm + ctx.wm * 64 + mi * 16 + g);
            const size_t row1 = row0 + 8;
#pragma unroll
            for (int ni = 0; ni < 4; ++ni) {
                const int posu = (colb >> 1) + ni * 4 + t;
                Cu[row0 * (EMB / 2) + posu] =
                    h2pack(ctx.c[mi][ni][0] + bj[ni].x,
                           ctx.c[mi][ni][1] + bj[ni].y);
                Cu[row1 * (EMB / 2) + posu] =
                    h2pack(ctx.c[mi][ni][2] + bj[ni].x,
                           ctx.c[mi][ni][3] + bj[ni].y);
            }
        }
    }
}

// ============================================================================
// Final projection GEMM: fp32 row-major output.
// ============================================================================
__global__ void __launch_bounds__(256, 2)
gemm_out_kernel(const __half* __restrict__ A, const __half* __restrict__ WT,
                const float* __restrict__ bias, float* __restrict__ C)
{
    extern __shared__ uint32_t smu[];
    const uint32_t sb = smem_u32(smu);
    const int tid = threadIdx.x;
    const int bn = blockIdx.x * GBN;
    const int bm = blockIdx.y * GBM;

    GemmCtx ctx;
    gemm_mainloop(A + (size_t)bm * EMB, WT + (size_t)bn * EMB, sb, tid, ctx);

    const int colb = bn + ctx.wn * 32;
    const int g = ctx.g, t = ctx.t;
    float2 bj[4];
#pragma unroll
    for (int ni = 0; ni < 4; ++ni) {
        bj[ni].x = bias[colb + ni * 8 + 2 * t];
        bj[ni].y = bias[colb + ni * 8 + 2 * t + 1];
    }
#pragma unroll
    for (int mi = 0; mi < 4; ++mi) {
        const size_t row0 = (size_t)(bm + ctx.wm * 64 + mi * 16 + g);
        const size_t row1 = row0 + 8;
#pragma unroll
        for (int ni = 0; ni < 4; ++ni) {
            const int col = colb + ni * 8 + 2 * t;
            float2 o0, o1;
            o0.x = ctx.c[mi][ni][0] + bj[ni].x;
            o0.y = ctx.c[mi][ni][1] + bj[ni].y;
            o1.x = ctx.c[mi][ni][2] + bj[ni].x;
            o1.y = ctx.c[mi][ni][3] + bj[ni].y;
            *(float2*)&C[row0 * EMB + col] = o0;
            *(float2*)&C[row1 * EMB + col] = o1;
        }
    }
}

// ============================================================================
// Flash attention (unchanged from R11): fp16 m16n8k16, warp-owns-rows,
// no-max softmax, Q frags in regs, P overlaid on Q smem, cp.async K/V.
// ============================================================================
#define RSQP 40
#define RSK  40
#define RSV  36
#define AOFF_QP 0                              // [128][RSQP] u32 (Q then P)
#define AOFF_K  (128 * RSQP)                   // 2 x [64][RSK]
#define AOFF_V  (AOFF_K + 2 * 64 * RSK)        // 2 x [64][RSV]
#define ATT_SMEM ((AOFF_V + 2 * 64 * RSV) * 4) // 59,392 B -> 2 CTAs/SM

__global__ void __launch_bounds__(256, 2)
attn_mma_kernel(const __half* __restrict__ Q, const __half* __restrict__ K,
                const __half* __restrict__ V, __half* __restrict__ O)
{
    extern __shared__ uint32_t smu[];
    const uint32_t sb = smem_u32(smu);

    const uint32_t QPsU = sb + AOFF_QP * 4;
    const uint32_t KsU[2] = { sb + AOFF_K * 4, sb + (AOFF_K + 64 * RSK) * 4 };
    const uint32_t VsU[2] = { sb + AOFF_V * 4, sb + (AOFF_V + 64 * RSV) * 4 };

    const int tid = threadIdx.x;
    const int qt = blockIdx.x;           // 0..15
    const int bh = blockIdx.y;           // 0..31
    const int b  = bh >> 4;
    const int hd = bh & 15;
    const int q0 = qt * 128;

    const __half* Qg = Q + (size_t)(b * SEQ + q0) * EMB + hd * HDIM;
    const __half* Kg = K + (size_t)b * SEQ * EMB + hd * HDIM;
    const __half* Vg = V + (size_t)b * SEQ * EMB + hd * HDIM;

    const int w    = tid >> 5;      // 0..7 : q-rows 16w..16w+15
    const int lane = tid & 31;
    const int g    = lane >> 2;
    const int t    = lane & 3;
    const int rowg = 16 * w + g;

    const int cq = tid & 7;         // 16B chunk within 64-half row
    const int rr = tid >> 3;        // 0..31

    // ---- stage Q (128 rows), K0/V0 (64 rows each) via cp.async ----
#pragma unroll
    for (int p = 0; p < 4; ++p) {
        int r = rr + 32 * p;
        CP_ASYNC16(QPsU + (uint32_t)((r * RSQP + cq * 4) * 4),
                   Qg + (size_t)r * EMB + cq * 8);
    }
#pragma unroll
    for (int p = 0; p < 2; ++p) {
        int r = rr + 32 * p;
        CP_ASYNC16(KsU[0] + (uint32_t)((r * RSK + cq * 4) * 4),
                   Kg + (size_t)r * EMB + cq * 8);
        CP_ASYNC16(VsU[0] + (uint32_t)((r * RSV + cq * 4) * 4),
                   Vg + (size_t)r * EMB + cq * 8);
    }
    CP_COMMIT();
    CP_WAIT0();
    __syncthreads();

    // ---- hoist Q fragments (4 ksteps of 16 halves) ----
    uint32_t qf[4][4];
    const uint32_t aQbase = QPsU + (uint32_t)((rowg * RSQP + 2 * t) * 4);
#pragma unroll
    for (int ks = 0; ks < 4; ++ks) {
        LDS_V2(qf[ks][0], qf[ks][2], aQbase + (uint32_t)(ks * 8 * 4));
        LDS_V2(qf[ks][1], qf[ks][3],
               aQbase + (uint32_t)(ks * 8 * 4) + 8 * RSQP * 4);
    }

    float o[8][4];
#pragma unroll
    for (int ni = 0; ni < 8; ++ni)
#pragma unroll
        for (int j = 0; j < 4; ++j) o[ni][j] = 0.f;
    float lp0 = 0.f, lp1 = 0.f;

    // P row pointers (overlay on Q smem; warp-private rows)
    const uint32_t prow0 = QPsU + (uint32_t)((rowg * RSQP) * 4);
    const uint32_t prow1 = prow0 + (uint32_t)(8 * RSQP * 4);
    const uint32_t aPbase = aQbase;

    // ldmatrix per-lane base: row (lane&15), half-col 8*(lane>>4)
    const uint32_t vlane = (uint32_t)(((lane & 15) * RSV + 4 * (lane >> 4)) * 4);

    const int NT = SEQ / 64;   // 32
    for (int kt = 0; kt < NT; ++kt) {
        const int cur = kt & 1;

        CP_WAIT0();
        __syncthreads();

        if (kt + 1 < NT) {
            const int nxt = cur ^ 1;
            const int k0n = (kt + 1) * 64;
#pragma unroll
            for (int p = 0; p < 2; ++p) {
                int r = rr + 32 * p;
                CP_ASYNC16(KsU[nxt] + (uint32_t)((r * RSK + cq * 4) * 4),
                           Kg + (size_t)(k0n + r) * EMB + cq * 8);
                CP_ASYNC16(VsU[nxt] + (uint32_t)((r * RSV + cq * 4) * 4),
                           Vg + (size_t)(k0n + r) * EMB + cq * 8);
            }
            CP_COMMIT();
        }

        // ---- S = Q @ K^T (warp tile 16 x 64) ----
        float s[8][4];
#pragma unroll
        for (int ni = 0; ni < 8; ++ni)
#pragma unroll
            for (int j = 0; j < 4; ++j) s[ni][j] = 0.f;

#pragma unroll
        for (int ks = 0; ks < 4; ++ks) {
#pragma unroll
            for (int ni = 0; ni < 8; ++ni) {
                uint32_t bf[2];
                LDS_V2(bf[0], bf[1],
                       KsU[cur] + (uint32_t)(((ni * 8 + g) * RSK
                                              + ks * 8 + 2 * t) * 4));
                MMA_F16(s[ni], qf[ks], bf);
            }
        }

        // ---- p = exp2(s); partial l; write P (half2, pair-permuted) ----
#pragma unroll
        for (int j = 0; j < 4; ++j) {
            float p00 = ex2(s[2 * j][0]);
            float p01 = ex2(s[2 * j][1]);
            float p02 = ex2(s[2 * j][2]);
            float p03 = ex2(s[2 * j][3]);
            float p10 = ex2(s[2 * j + 1][0]);
            float p11 = ex2(s[2 * j + 1][1]);
            float p12 = ex2(s[2 * j + 1][2]);
            float p13 = ex2(s[2 * j + 1][3]);
            lp0 += p00 + p01 + p10 + p11;
            lp1 += p02 + p03 + p12 + p13;
            STS_V2(prow0 + (uint32_t)((j * 8 + 2 * t) * 4),
                   h2pack(p00, p01), h2pack(p10, p11));
            STS_V2(prow1 + (uint32_t)((j * 8 + 2 * t) * 4),
                   h2pack(p02, p03), h2pack(p12, p13));
        }
        __syncwarp();

        // ---- O += P @ V (V via ldmatrix.trans) ----
#pragma unroll
        for (int ks = 0; ks < 4; ++ks) {
            uint32_t af[4];
            LDS_V2(af[0], af[2], aPbase + (uint32_t)(ks * 8 * 4));
            LDS_V2(af[1], af[3],
                   aPbase + (uint32_t)(ks * 8 * 4) + 8 * RSQP * 4);
            const uint32_t vrow = VsU[cur] + vlane
                                + (uint32_t)(ks * 16 * RSV * 4);
#pragma unroll
            for (int d16 = 0; d16 < 4; ++d16) {
                uint32_t r0, r1, r2, r3;
                LDSM_X4_T(r0, r1, r2, r3, vrow + (uint32_t)(d16 * 8 * 4));
                uint32_t b0[2] = { r0, r1 };
                uint32_t b1[2] = { r2, r3 };
                MMA_F16(o[2 * d16],     af, b0);
                MMA_F16(o[2 * d16 + 1], af, b1);
            }
        }
    }

    // ---- reduce l over t-lanes, normalize, store half2 pair-permuted ----
    lp0 += __shfl_xor_sync(0xffffffffu, lp0, 1);
    lp0 += __shfl_xor_sync(0xffffffffu, lp0, 2);
    lp1 += __shfl_xor_sync(0xffffffffu, lp1, 1);
    lp1 += __shfl_xor_sync(0xffffffffu, lp1, 2);
    const float inv0 = 1.f / lp0;
    const float inv1 = 1.f / lp1;

    uint32_t* Ou = (uint32_t*)O;
    const size_t tok0 = (size_t)(b * SEQ + q0 + rowg);
    const size_t tok1 = tok0 + 8;
#pragma unroll
    for (int ni = 0; ni < 8; ++ni) {
        const int grp = hd * 4 + (ni >> 1);
        const int pos = grp * 8 + perm8((ni & 1) * 4 + t);
        Ou[tok0 * (EMB / 2) + pos] = h2pack(o[ni][0] * inv0, o[ni][1] * inv0);
        Ou[tok1 * (EMB / 2) + pos] = h2pack(o[ni][2] * inv1, o[ni][3] * inv1);
    }
}

// ============================================================================
// launch
// ============================================================================
extern "C" void kernel_launch(void* const* d_in, const int* in_sizes, int n_in,
                              void* d_out, int out_size)
{
    const float* xv = (const float*)d_in[0];
    const float* xk = (const float*)d_in[1];
    const float* xq = (const float*)d_in[2];
    const float* Wq = (const float*)d_in[3];
    const float* bq = (const float*)d_in[4];
    const float* Wk = (const float*)d_in[5];
    const float* bk = (const float*)d_in[6];
    const float* Wv = (const float*)d_in[7];
    const float* bv = (const float*)d_in[8];
    const float* Wo = (const float*)d_in[9];
    const float* bo = (const float*)d_in[10];
    float* out = (float*)d_out;

    __half *Qd, *Kd, *Vd, *Cd, *WTd, *Xd;
    cudaGetSymbolAddress((void**)&Qd, g_Q);
    cudaGetSymbolAddress((void**)&Kd, g_K);
    cudaGetSymbolAddress((void**)&Vd, g_V);
    cudaGetSymbolAddress((void**)&Cd, g_C);
    cudaGetSymbolAddress((void**)&WTd, g_WT);
    cudaGetSymbolAddress((void**)&Xd, g_X);

    __half* WoT = WTd + 3ll * EMB * EMB;

    // merged pre-round (xq -> z0, xk -> z1, xv -> z2)
    dim3 prgrid((MROWS * EMB / 16) / 256, 3);   // (1024, 3)
    preround3_kernel<<<prgrid, 256>>>(xq, xk, xv, Xd);

    // merged transposes (Wq,Wk,Wv,Wo -> WT[0..3])
    dim3 tgrid(EMB / 32, EMB / 32, 4);
    dim3 tblk(32, 8);
    transpose4_kernel<<<tgrid, tblk>>>(Wq, Wk, Wv, Wo, WTd);

    cudaFuncSetAttribute(gemm_qkv_kernel,
                         cudaFuncAttributeMaxDynamicSharedMemorySize, GSMEM_TOTAL);
    cudaFuncSetAttribute(gemm_out_kernel,
                         cudaFuncAttributeMaxDynamicSharedMemorySize, GSMEM_TOTAL);

    // merged Q/K/V projections
    dim3 qkvgrid(EMB / GBN, MROWS / GBM, 3);   // (8, 32, 3)
    gemm_qkv_kernel<<<qkvgrid, 256, GSMEM_TOTAL>>>(Xd, WTd, bq, bk, bv,
                                                   Qd, Kd, Vd);

    cudaFuncSetAttribute(attn_mma_kernel,
                         cudaFuncAttributeMaxDynamicSharedMemorySize, ATT_SMEM);
    dim3 agrid(SEQ / 128, BATCH * HEADS);  // (16, 32)
    attn_mma_kernel<<<agrid, 256, ATT_SMEM>>>(Qd, Kd, Vd, Cd);

    dim3 ggrid(EMB / GBN, MROWS / GBM);   // (8, 32)
    gemm_out_kernel<<<ggrid, 256, GSMEM_TOTAL>>>(Cd, WoT, bo, out);
}

// round 13
// speedup vs baseline: 2.3316x; 1.0792x over previous
#include <cuda_runtime.h>
#include <cuda_fp16.h>
#include <cstdint>
#include <math.h>

// Problem constants
#define BATCH 2
#define SEQ   2048
#define EMB   1024
#define HEADS 16
#define HDIM  64
#define MROWS (BATCH * SEQ)   // 4096

// ---------------- scratch (device globals; no allocations allowed) ---------
__device__ __half g_Q[MROWS * EMB];     // Q proj: scaled, rounded, plain [token][dim]
__device__ __half g_K[MROWS * EMB];     // K proj: rounded, plain [token][dim]
__device__ __half g_V[MROWS * EMB];     // V proj: rounded, plain [token][dim]
__device__ __half g_C[MROWS * EMB];     // attention out: rounded, pair-permuted dims
__device__ __half g_WT[4][EMB * EMB];   // W^T: rounded, pair-permuted k
__device__ __half g_X[3][MROWS * EMB];  // xq/xk/xv: rounded, pair-permuted k

#define QSCALE 0.18033688f   // 0.125 * log2(e)

// ============================================================================
// helpers
// ============================================================================
__device__ __forceinline__ uint32_t smem_u32(const void* p) {
    uint32_t a;
    asm("{ .reg .u64 t; cvta.to.shared.u64 t, %1; cvt.u32.u64 %0, t; }"
        : "=r"(a) : "l"(p));
    return a;
}

// pack two f32 -> f16x2 (lo = first arg)
__device__ __forceinline__ uint32_t h2pack(float lo, float hi) {
    uint32_t r;
    asm("cvt.rn.f16x2.f32 %0, %1, %2;" : "=r"(r) : "f"(hi), "f"(lo));
    return r;
}

__device__ __forceinline__ float ex2(float x) {
    float r;
    asm("ex2.approx.f32 %0, %1;" : "=f"(r) : "f"(x));
    return r;
}

#define MMA_F16(c, a, b)                                                      \
    asm volatile("mma.sync.aligned.m16n8k16.row.col.f32.f16.f16.f32 "         \
                 "{%0,%1,%2,%3}, {%4,%5,%6,%7}, {%8,%9}, {%0,%1,%2,%3};"      \
                 : "+f"((c)[0]), "+f"((c)[1]), "+f"((c)[2]), "+f"((c)[3])     \
                 : "r"((a)[0]), "r"((a)[1]), "r"((a)[2]), "r"((a)[3]),        \
                   "r"((b)[0]), "r"((b)[1]))

#define LDS_V2(r0, r1, addr)                                                  \
    asm volatile("ld.shared.v2.b32 {%0,%1}, [%2];"                            \
                 : "=r"(r0), "=r"(r1) : "r"(addr))

#define LDSM_X4(r0, r1, r2, r3, addr)                                         \
    asm volatile("ldmatrix.sync.aligned.m8n8.x4.shared.b16 "                  \
                 "{%0,%1,%2,%3}, [%4];"                                       \
                 : "=r"(r0), "=r"(r1), "=r"(r2), "=r"(r3) : "r"(addr))

#define LDSM_X4_T(r0, r1, r2, r3, addr)                                       \
    asm volatile("ldmatrix.sync.aligned.m8n8.x4.trans.shared.b16 "            \
                 "{%0,%1,%2,%3}, [%4];"                                       \
                 : "=r"(r0), "=r"(r1), "=r"(r2), "=r"(r3) : "r"(addr))

#define CP_ASYNC16(dst, src)                                                  \
    asm volatile("cp.async.cg.shared.global [%0], [%1], 16;"                  \
                 :: "r"(dst), "l"(src))
#define CP_COMMIT() asm volatile("cp.async.commit_group;" ::: "memory")
#define CP_WAIT0()  asm volatile("cp.async.wait_group 0;" ::: "memory")

// pair-index permutation within a 16-half (8-pair) group
__device__ __forceinline__ int perm8(int p) {
    return ((p & 3) << 1) | (p >> 2);
}

// ============================================================================
// Merged pre-round (xq/xk/xv) to fp16 + pair-permute per 16-half group.
// ============================================================================
__global__ void __launch_bounds__(256)
preround3_kernel(const float* __restrict__ xq, const float* __restrict__ xk,
                 const float* __restrict__ xv, __half* __restrict__ Ybase)
{
    const int z = blockIdx.y;
    const float* X = (z == 0) ? xq : (z == 1) ? xk : xv;
    __half* Y = Ybase + (size_t)z * MROWS * EMB;

    size_t i16 = (size_t)blockIdx.x * 256 + threadIdx.x;
    const float* xp = X + i16 * 16;
    uint32_t* yp = (uint32_t*)Y + i16 * 8;
    float x[16];
#pragma unroll
    for (int q = 0; q < 4; ++q) {
        float4 v = *(const float4*)&xp[q * 4];
        x[q * 4 + 0] = v.x; x[q * 4 + 1] = v.y;
        x[q * 4 + 2] = v.z; x[q * 4 + 3] = v.w;
    }
    uint32_t o[8];
#pragma unroll
    for (int p = 0; p < 8; ++p)
        o[perm8(p)] = h2pack(x[2 * p], x[2 * p + 1]);
    uint4 w0 = { o[0], o[1], o[2], o[3] };
    uint4 w1 = { o[4], o[5], o[6], o[7] };
    *(uint4*)&yp[0] = w0;
    *(uint4*)&yp[4] = w1;
}

// ============================================================================
// Merged weight transpose (4 weights) + fp16 round + pair-permute.
// ============================================================================
__global__ void __launch_bounds__(256)
transpose4_kernel(const float* __restrict__ Wq, const float* __restrict__ Wk,
                  const float* __restrict__ Wv, const float* __restrict__ Wo,
                  __half* __restrict__ WTbase)
{
    const int z = blockIdx.z;
    const float* W = (z == 0) ? Wq : (z == 1) ? Wk : (z == 2) ? Wv : Wo;
    __half* WT = WTbase + (size_t)z * EMB * EMB;

    __shared__ float tile[32][33];
    int x = blockIdx.x * 32 + threadIdx.x;   // n
    int y = blockIdx.y * 32 + threadIdx.y;   // k
#pragma unroll
    for (int j = 0; j < 32; j += 8)
        tile[threadIdx.y + j][threadIdx.x] = W[(size_t)(y + j) * EMB + x];
    __syncthreads();
    const int cu = threadIdx.x & 15;
    const int nl0 = threadIdx.y + 8 * (threadIdx.x >> 4);
    uint32_t* Wu = (uint32_t*)WT;
#pragma unroll
    for (int j = 0; j < 32; j += 16) {
        int nl = nl0 + j;
        uint32_t h = h2pack(tile[2 * cu][nl], tile[2 * cu + 1][nl]);
        size_t n = (size_t)(blockIdx.x * 32 + nl);
        Wu[n * (EMB / 2) + blockIdx.y * 16 + (cu >> 3) * 8 + perm8(cu & 7)] = h;
    }
}

// ============================================================================
// fp16 mma.sync GEMM mainloop (shared).
// ============================================================================
#define GBM 128
#define GBN 128
#define RSTR 40                      // u32 per row (32 data + 8 pad)
#define TILE_U (128 * RSTR)
#define GSMEM_TOTAL (4 * TILE_U * 4)

struct GemmCtx {
    int wm, wn, g, t;
    float c[4][4][4];
};

__device__ __forceinline__ void gemm_mainloop(
    const __half* __restrict__ Ap, const __half* __restrict__ Bp,
    uint32_t sb, int tid, GemmCtx& ctx)
{
    const int w    = tid >> 5;
    ctx.wm = w & 1;
    ctx.wn = w >> 1;
    const int lane = tid & 31;
    ctx.g = lane >> 2;
    ctx.t = lane & 3;

    const int s  = tid & 7;
    const int r0 = tid >> 3;

    const uint32_t AsU[2] = { sb,                  sb + TILE_U * 4 };
    const uint32_t BsU[2] = { sb + 2 * TILE_U * 4, sb + 3 * TILE_U * 4 };

#pragma unroll
    for (int mi = 0; mi < 4; ++mi)
#pragma unroll
        for (int ni = 0; ni < 4; ++ni)
#pragma unroll
            for (int j = 0; j < 4; ++j) ctx.c[mi][ni][j] = 0.f;

    const uint32_t dOff = (uint32_t)((r0 * RSTR + s * 4) * 4);
    const size_t   gOff = (size_t)r0 * EMB + s * 8;   // halves

    {
#pragma unroll
        for (int p = 0; p < 4; ++p) {
            CP_ASYNC16(AsU[0] + dOff + (uint32_t)(32 * p * RSTR * 4),
                       Ap + gOff + (size_t)32 * p * EMB);
            CP_ASYNC16(BsU[0] + dOff + (uint32_t)(32 * p * RSTR * 4),
                       Bp + gOff + (size_t)32 * p * EMB);
        }
        CP_COMMIT();
    }

    const int NKT = EMB / 64;   // 16
    for (int kt = 0; kt < NKT; ++kt) {
        const int b = kt & 1;

        if (kt + 1 < NKT) {
            const int nb = b ^ 1;
            const size_t k0 = (size_t)(kt + 1) * 64;   // halves
#pragma unroll
            for (int p = 0; p < 4; ++p) {
                CP_ASYNC16(AsU[nb] + dOff + (uint32_t)(32 * p * RSTR * 4),
                           Ap + gOff + k0 + (size_t)32 * p * EMB);
                CP_ASYNC16(BsU[nb] + dOff + (uint32_t)(32 * p * RSTR * 4),
                           Bp + gOff + k0 + (size_t)32 * p * EMB);
            }
            CP_COMMIT();
            asm volatile("cp.async.wait_group 1;" ::: "memory");
        } else {
            CP_WAIT0();
        }
        __syncthreads();

        const uint32_t aU = AsU[b];
        const uint32_t bU = BsU[b];
#pragma unroll
        for (int ks = 0; ks < 4; ++ks) {
            uint32_t af[4][4], bf[4][2];
#pragma unroll
            for (int mi = 0; mi < 4; ++mi) {
                uint32_t addr0 = aU + (uint32_t)(((ctx.wm * 64 + mi * 16 + ctx.g) * RSTR
                                                 + ks * 8 + 2 * ctx.t) * 4);
                LDS_V2(af[mi][0], af[mi][2], addr0);
                LDS_V2(af[mi][1], af[mi][3], addr0 + 8 * RSTR * 4);
            }
#pragma unroll
            for (int ni = 0; ni < 4; ++ni) {
                uint32_t addr = bU + (uint32_t)(((ctx.wn * 32 + ni * 8 + ctx.g) * RSTR
                                                + ks * 8 + 2 * ctx.t) * 4);
                LDS_V2(bf[ni][0], bf[ni][1], addr);
            }
#pragma unroll
            for (int mi = 0; mi < 4; ++mi)
#pragma unroll
                for (int ni = 0; ni < 4; ++ni)
                    MMA_F16(ctx.c[mi][ni], af[mi], bf[ni]);
        }
        __syncthreads();
    }
}

// ============================================================================
// Merged QKV GEMM: all outputs plain [token][dim] half (Q scaled by QSCALE).
// ============================================================================
__global__ void __launch_bounds__(256, 2)
gemm_qkv_kernel(const __half* __restrict__ Xbase, const __half* __restrict__ WTbase,
                const float* __restrict__ bq, const float* __restrict__ bk,
                const float* __restrict__ bv,
                __half* __restrict__ Qd, __half* __restrict__ Kd,
                __half* __restrict__ Vd)
{
    extern __shared__ uint32_t smu[];
    const uint32_t sb = smem_u32(smu);
    const int tid = threadIdx.x;
    const int bn = blockIdx.x * GBN;
    const int bm = blockIdx.y * GBM;
    const int z  = blockIdx.z;

    const __half* A  = Xbase  + (size_t)z * MROWS * EMB + (size_t)bm * EMB;
    const __half* Bw = WTbase + (size_t)z * EMB * EMB   + (size_t)bn * EMB;
    const float* bias = (z == 0) ? bq : (z == 1) ? bk : bv;
    __half* outp = (z == 0) ? Qd : (z == 1) ? Kd : Vd;

    GemmCtx ctx;
    gemm_mainloop(A, Bw, sb, tid, ctx);

    const int colb = bn + ctx.wn * 32;
    const int g = ctx.g, t = ctx.t;
    const float sc = (z == 0) ? QSCALE : 1.f;
    float2 bj[4];
#pragma unroll
    for (int ni = 0; ni < 4; ++ni) {
        bj[ni].x = bias[colb + ni * 8 + 2 * t];
        bj[ni].y = bias[colb + ni * 8 + 2 * t + 1];
    }

    uint32_t* Cu = (uint32_t*)outp;
#pragma unroll
    for (int mi = 0; mi < 4; ++mi) {
        const size_t row0 = (size_t)(bm + ctx.wm * 64 + mi * 16 + g);
        const size_t row1 = row0 + 8;
#pragma unroll
        for (int ni = 0; ni < 4; ++ni) {
            const int posu = (colb >> 1) + ni * 4 + t;
            Cu[row0 * (EMB / 2) + posu] =
                h2pack((ctx.c[mi][ni][0] + bj[ni].x) * sc,
                       (ctx.c[mi][ni][1] + bj[ni].y) * sc);
            Cu[row1 * (EMB / 2) + posu] =
                h2pack((ctx.c[mi][ni][2] + bj[ni].x) * sc,
                       (ctx.c[mi][ni][3] + bj[ni].y) * sc);
        }
    }
}

// ============================================================================
// Final projection GEMM: fp32 row-major output.
// ============================================================================
__global__ void __launch_bounds__(256, 2)
gemm_out_kernel(const __half* __restrict__ A, const __half* __restrict__ WT,
                const float* __restrict__ bias, float* __restrict__ C)
{
    extern __shared__ uint32_t smu[];
    const uint32_t sb = smem_u32(smu);
    const int tid = threadIdx.x;
    const int bn = blockIdx.x * GBN;
    const int bm = blockIdx.y * GBM;

    GemmCtx ctx;
    gemm_mainloop(A + (size_t)bm * EMB, WT + (size_t)bn * EMB, sb, tid, ctx);

    const int colb = bn + ctx.wn * 32;
    const int g = ctx.g, t = ctx.t;
    float2 bj[4];
#pragma unroll
    for (int ni = 0; ni < 4; ++ni) {
        bj[ni].x = bias[colb + ni * 8 + 2 * t];
        bj[ni].y = bias[colb + ni * 8 + 2 * t + 1];
    }
#pragma unroll
    for (int mi = 0; mi < 4; ++mi) {
        const size_t row0 = (size_t)(bm + ctx.wm * 64 + mi * 16 + g);
        const size_t row1 = row0 + 8;
#pragma unroll
        for (int ni = 0; ni < 4; ++ni) {
            const int col = colb + ni * 8 + 2 * t;
            float2 o0, o1;
            o0.x = ctx.c[mi][ni][0] + bj[ni].x;
            o0.y = ctx.c[mi][ni][1] + bj[ni].y;
            o1.x = ctx.c[mi][ni][2] + bj[ni].x;
            o1.y = ctx.c[mi][ni][3] + bj[ni].y;
            *(float2*)&C[row0 * EMB + col] = o0;
            *(float2*)&C[row1 * EMB + col] = o1;
        }
    }
}

// ============================================================================
// Flash attention, fp16 m16n8k16, register-resident P (S-frag -> A-frag
// identity), all operands canonical plain layout, Q/K via ldmatrix,
// V via ldmatrix.trans. Warp-owns-rows (8 warps x 16 q-rows), no-max softmax,
// cp.async double-buffered K/V. 2 CTAs/SM.
// ============================================================================
#define RS 36                                 // u32 stride (ldmatrix-friendly)
#define AOFF_Q 0                              // [128][RS]
#define AOFF_K (128 * RS)                     // 2 x [64][RS]
#define AOFF_V (AOFF_K + 2 * 64 * RS)         // 2 x [64][RS]
#define ATT_SMEM ((AOFF_V + 2 * 64 * RS) * 4) // 55,296 B -> 2 CTAs/SM

__global__ void __launch_bounds__(256, 2)
attn_mma_kernel(const __half* __restrict__ Q, const __half* __restrict__ K,
                const __half* __restrict__ V, __half* __restrict__ O)
{
    extern __shared__ uint32_t smu[];
    const uint32_t sb = smem_u32(smu);

    const uint32_t QsU = sb + AOFF_Q * 4;
    const uint32_t KsU[2] = { sb + AOFF_K * 4, sb + (AOFF_K + 64 * RS) * 4 };
    const uint32_t VsU[2] = { sb + AOFF_V * 4, sb + (AOFF_V + 64 * RS) * 4 };

    const int tid = threadIdx.x;
    const int qt = blockIdx.x;           // 0..15
    const int bh = blockIdx.y;           // 0..31
    const int b  = bh >> 4;
    const int hd = bh & 15;
    const int q0 = qt * 128;

    const __half* Qg = Q + (size_t)(b * SEQ + q0) * EMB + hd * HDIM;
    const __half* Kg = K + (size_t)b * SEQ * EMB + hd * HDIM;
    const __half* Vg = V + (size_t)b * SEQ * EMB + hd * HDIM;

    const int w    = tid >> 5;      // 0..7 : q-rows 16w..16w+15
    const int lane = tid & 31;
    const int g    = lane >> 2;
    const int t    = lane & 3;
    const int rowg = 16 * w + g;

    const int cq = tid & 7;         // 16B chunk within 64-half row
    const int rr = tid >> 3;        // 0..31

    // ---- stage Q (128 rows), K0/V0 (64 rows each) via cp.async ----
#pragma unroll
    for (int p = 0; p < 4; ++p) {
        int r = rr + 32 * p;
        CP_ASYNC16(QsU + (uint32_t)((r * RS + cq * 4) * 4),
                   Qg + (size_t)r * EMB + cq * 8);
    }
#pragma unroll
    for (int p = 0; p < 2; ++p) {
        int r = rr + 32 * p;
        CP_ASYNC16(KsU[0] + (uint32_t)((r * RS + cq * 4) * 4),
                   Kg + (size_t)r * EMB + cq * 8);
        CP_ASYNC16(VsU[0] + (uint32_t)((r * RS + cq * 4) * 4),
                   Vg + (size_t)r * EMB + cq * 8);
    }
    CP_COMMIT();
    CP_WAIT0();
    __syncthreads();

    // ---- hoist Q a-frags via ldmatrix x4 (one per kstep) ----
    // lanes 0-7: m0 rows 0-7 oct0 | 8-15: m1 rows 8-15 oct0
    // lanes 16-23: m2 rows 0-7 oct1 | 24-31: m3 rows 8-15 oct1
    uint32_t qf[4][4];
    {
        const int laneRowA = ((lane & 8) ? 8 : 0) + (lane & 7);
        const int colOctA  = (lane >> 4) * 4;
        const uint32_t qbase = QsU
            + (uint32_t)(((w * 16 + laneRowA) * RS + colOctA) * 4);
#pragma unroll
        for (int ks = 0; ks < 4; ++ks)
            LDSM_X4(qf[ks][0], qf[ks][1], qf[ks][2], qf[ks][3],
                    qbase + (uint32_t)(ks * 8 * 4));
    }

    float o[8][4];
#pragma unroll
    for (int ni = 0; ni < 8; ++ni)
#pragma unroll
        for (int j = 0; j < 4; ++j) o[ni][j] = 0.f;
    float lp0 = 0.f, lp1 = 0.f;

    // K b-frag ldmatrix lane base:
    // lanes 0-7: m0 keys 0-7 oct0 | 8-15: m1 keys 0-7 oct1
    // lanes 16-23: m2 keys 8-15 oct0 | 24-31: m3 keys 8-15 oct1
    const int laneRowB = ((lane >> 4) << 3) + (lane & 7);
    const int colOctB  = (lane & 8) ? 4 : 0;

    // V ldmatrix.trans lane base: rows (lane&15) = keys, col oct (lane>>4)
    const uint32_t vlane = (uint32_t)(((lane & 15) * RS + 4 * (lane >> 4)) * 4);

    const int NT = SEQ / 64;   // 32
    for (int kt = 0; kt < NT; ++kt) {
        const int cur = kt & 1;

        CP_WAIT0();
        __syncthreads();

        if (kt + 1 < NT) {
            const int nxt = cur ^ 1;
            const int k0n = (kt + 1) * 64;
#pragma unroll
            for (int p = 0; p < 2; ++p) {
                int r = rr + 32 * p;
                CP_ASYNC16(KsU[nxt] + (uint32_t)((r * RS + cq * 4) * 4),
                           Kg + (size_t)(k0n + r) * EMB + cq * 8);
                CP_ASYNC16(VsU[nxt] + (uint32_t)((r * RS + cq * 4) * 4),
                           Vg + (size_t)(k0n + r) * EMB + cq * 8);
            }
            CP_COMMIT();
        }

        // ---- S = Q @ K^T (warp tile 16 x 64) via ldmatrix b-frags ----
        float s[8][4];
#pragma unroll
        for (int ni = 0; ni < 8; ++ni)
#pragma unroll
            for (int j = 0; j < 4; ++j) s[ni][j] = 0.f;

#pragma unroll
        for (int ks = 0; ks < 4; ++ks) {
#pragma unroll
            for (int kb = 0; kb < 4; ++kb) {    // 16-key blocks
                uint32_t r0, r1, r2, r3;
                uint32_t a = KsU[cur]
                    + (uint32_t)(((kb * 16 + laneRowB) * RS
                                  + ks * 8 + colOctB) * 4);
                LDSM_X4(r0, r1, r2, r3, a);
                uint32_t b0[2] = { r0, r1 };
                uint32_t b1[2] = { r2, r3 };
                MMA_F16(s[2 * kb],     qf[ks], b0);
                MMA_F16(s[2 * kb + 1], qf[ks], b1);
            }
        }

        // ---- p = exp2(s) -> PV a-frags in REGISTERS (no smem round trip) ----
        uint32_t pf[4][4];
#pragma unroll
        for (int ks = 0; ks < 4; ++ks) {
            float e00 = ex2(s[2 * ks][0]);
            float e01 = ex2(s[2 * ks][1]);
            float e02 = ex2(s[2 * ks][2]);
            float e03 = ex2(s[2 * ks][3]);
            float e10 = ex2(s[2 * ks + 1][0]);
            float e11 = ex2(s[2 * ks + 1][1]);
            float e12 = ex2(s[2 * ks + 1][2]);
            float e13 = ex2(s[2 * ks + 1][3]);
            lp0 += e00 + e01 + e10 + e11;
            lp1 += e02 + e03 + e12 + e13;
            pf[ks][0] = h2pack(e00, e01);   // a0 = P[g][16ks+2t..]
            pf[ks][1] = h2pack(e02, e03);   // a1 = P[g+8][16ks+2t..]
            pf[ks][2] = h2pack(e10, e11);   // a2 = P[g][16ks+8+2t..]
            pf[ks][3] = h2pack(e12, e13);   // a3 = P[g+8][16ks+8+2t..]
        }

        // ---- O += P @ V (V via ldmatrix.trans) ----
#pragma unroll
        for (int ks = 0; ks < 4; ++ks) {
            const uint32_t vrow = VsU[cur] + vlane
                                + (uint32_t)(ks * 16 * RS * 4);
#pragma unroll
            for (int d16 = 0; d16 < 4; ++d16) {
                uint32_t r0, r1, r2, r3;
                LDSM_X4_T(r0, r1, r2, r3, vrow + (uint32_t)(d16 * 8 * 4));
                uint32_t b0[2] = { r0, r1 };
                uint32_t b1[2] = { r2, r3 };
                MMA_F16(o[2 * d16],     pf[ks], b0);
                MMA_F16(o[2 * d16 + 1], pf[ks], b1);
            }
        }
    }

    // ---- reduce l over t-lanes, normalize, store half2 pair-permuted ----
    lp0 += __shfl_xor_sync(0xffffffffu, lp0, 1);
    lp0 += __shfl_xor_sync(0xffffffffu, lp0, 2);
    lp1 += __shfl_xor_sync(0xffffffffu, lp1, 1);
    lp1 += __shfl_xor_sync(0xffffffffu, lp1, 2);
    const float inv0 = 1.f / lp0;
    const float inv1 = 1.f / lp1;

    uint32_t* Ou = (uint32_t*)O;
    const size_t tok0 = (size_t)(b * SEQ + q0 + rowg);
    const size_t tok1 = tok0 + 8;
#pragma unroll
    for (int ni = 0; ni < 8; ++ni) {
        const int grp = hd * 4 + (ni >> 1);
        const int pos = grp * 8 + perm8((ni & 1) * 4 + t);
        Ou[tok0 * (EMB / 2) + pos] = h2pack(o[ni][0] * inv0, o[ni][1] * inv0);
        Ou[tok1 * (EMB / 2) + pos] = h2pack(o[ni][2] * inv1, o[ni][3] * inv1);
    }
}

// ============================================================================
// launch
// ============================================================================
extern "C" void kernel_launch(void* const* d_in, const int* in_sizes, int n_in,
                              void* d_out, int out_size)
{
    const float* xv = (const float*)d_in[0];
    const float* xk = (const float*)d_in[1];
    const float* xq = (const float*)d_in[2];
    const float* Wq = (const float*)d_in[3];
    const float* bq = (const float*)d_in[4];
    const float* Wk = (const float*)d_in[5];
    const float* bk = (const float*)d_in[6];
    const float* Wv = (const float*)d_in[7];
    const float* bv = (const float*)d_in[8];
    const float* Wo = (const float*)d_in[9];
    const float* bo = (const float*)d_in[10];
    float* out = (float*)d_out;

    __half *Qd, *Kd, *Vd, *Cd, *WTd, *Xd;
    cudaGetSymbolAddress((void**)&Qd, g_Q);
    cudaGetSymbolAddress((void**)&Kd, g_K);
    cudaGetSymbolAddress((void**)&Vd, g_V);
    cudaGetSymbolAddress((void**)&Cd, g_C);
    cudaGetSymbolAddress((void**)&WTd, g_WT);
    cudaGetSymbolAddress((void**)&Xd, g_X);

    __half* WoT = WTd + 3ll * EMB * EMB;

    dim3 prgrid((MROWS * EMB / 16) / 256, 3);   // (1024, 3)
    preround3_kernel<<<prgrid, 256>>>(xq, xk, xv, Xd);

    dim3 tgrid(EMB / 32, EMB / 32, 4);
    dim3 tblk(32, 8);
    transpose4_kernel<<<tgrid, tblk>>>(Wq, Wk, Wv, Wo, WTd);

    cudaFuncSetAttribute(gemm_qkv_kernel,
                         cudaFuncAttributeMaxDynamicSharedMemorySize, GSMEM_TOTAL);
    cudaFuncSetAttribute(gemm_out_kernel,
                         cudaFuncAttributeMaxDynamicSharedMemorySize, GSMEM_TOTAL);

    dim3 qkvgrid(EMB / GBN, MROWS / GBM, 3);   // (8, 32, 3)
    gemm_qkv_kernel<<<qkvgrid, 256, GSMEM_TOTAL>>>(Xd, WTd, bq, bk, bv,
                                                   Qd, Kd, Vd);

    cudaFuncSetAttribute(attn_mma_kernel,
                         cudaFuncAttributeMaxDynamicSharedMemorySize, ATT_SMEM);
    dim3 agrid(SEQ / 128, BATCH * HEADS);  // (16, 32)
    attn_mma_kernel<<<agrid, 256, ATT_SMEM>>>(Qd, Kd, Vd, Cd);

    dim3 ggrid(EMB / GBN, MROWS / GBM);   // (8, 32)
    gemm_out_kernel<<<ggrid, 256, GSMEM_TOTAL>>>(Cd, WoT, bo, out);
}